// round 1
// baseline (speedup 1.0000x reference)
#include <cuda_runtime.h>

#define HID  256
#define NS   32
#define IMGW 128
#define TPB  256

// One ray per block. 256 threads.
//   jg = tid & 63   -> owns hidden columns j0 = jg*4 .. j0+3
//   pg = tid >> 6   -> owns sample points  p  = pg*8 .. pg*8+7
// Layer2: acc[8 points][4 cols], W2 streamed through a 32-row SMEM tile.
// Layer3 folded into 4 output channels, reduced with warp shuffles (deterministic).
// Compositing by warp 0 with an inclusive shuffle scan over the 32 samples.

__global__ __launch_bounds__(TPB) void nerf_render_kernel(
    const float* __restrict__ Kmat, const float* __restrict__ T,
    const float* __restrict__ amin, const float* __restrict__ amax,
    const float* __restrict__ W1,   const float* __restrict__ b1,
    const float* __restrict__ W2,   const float* __restrict__ b2,
    const float* __restrict__ W3,   const float* __restrict__ b3,
    float* __restrict__ out)
{
    extern __shared__ float smem[];
    float* h1s      = smem;                 // [32][256] = 32KB
    float* ws       = smem + NS * HID;      // [32][256] = 32KB (W2 k-tile)
    float* partials = smem + 2 * NS * HID;  // [8 warps][8 pts][4 ch] = 1KB
    float* out4     = partials + 8 * 8 * 4; // [32 pts][4] = 512B

    const int tid = threadIdx.x;
    const int ray = blockIdx.x;
    const int px  = ray & (IMGW - 1);
    const int py  = ray >> 7;

    // ---------------- Ray setup (cheap, every thread) ----------------
    const float fx = Kmat[0], fy = Kmat[4], cx = Kmat[2], cy = Kmat[5];
    float u = px + 0.5f, v = py + 0.5f;
    float ddx = (u - cx) / fx, ddy = (v - cy) / fy, ddz = 1.0f;
    float rn = rsqrtf(ddx * ddx + ddy * ddy + ddz * ddz);
    ddx *= rn; ddy *= rn; ddz *= rn;
    const float d0 = T[0] * ddx + T[1] * ddy + T[2]  * ddz;
    const float d1 = T[4] * ddx + T[5] * ddy + T[6]  * ddz;
    const float d2 = T[8] * ddx + T[9] * ddy + T[10] * ddz;
    const float o0 = T[3], o1 = T[7], o2 = T[11];
    const float mn0 = amin[0], mn1 = amin[1], mn2 = amin[2];
    const float mx0 = amax[0], mx1 = amax[1], mx2 = amax[2];

    const float i0 = 1.0f / d0, i1 = 1.0f / d1, i2 = 1.0f / d2;
    const float a0 = (mn0 - o0) * i0, b0v = (mx0 - o0) * i0;
    const float a1 = (mn1 - o1) * i1, b1v = (mx1 - o1) * i1;
    const float a2 = (mn2 - o2) * i2, b2v = (mx2 - o2) * i2;
    const float tnear = fmaxf(0.0f,
        fmaxf(fminf(a0, b0v), fmaxf(fminf(a1, b1v), fminf(a2, b2v))));
    const float tfar = fminf(fmaxf(a0, b0v), fminf(fmaxf(a1, b1v), fmaxf(a2, b2v)));
    const bool hit = tnear < tfar;
    if (!hit) {
        if (tid == 0)
            reinterpret_cast<float4*>(out)[ray] = make_float4(0.f, 0.f, 0.f, 0.f);
        return;
    }
    const float tfar_s = tfar;
    const float span   = tfar_s - tnear;

    const float sclx = 2.0f / (mx0 - mn0);
    const float scly = 2.0f / (mx1 - mn1);
    const float sclz = 2.0f / (mx2 - mn2);

    const int jg = tid & 63;
    const int pg = tid >> 6;
    const int j0 = jg << 2;

    // ---------------- Layer 1: h1 = relu(nxyz @ W1 + b1) ----------------
    {
        const float4 w1r0 = __ldg(reinterpret_cast<const float4*>(W1) + jg);
        const float4 w1r1 = __ldg(reinterpret_cast<const float4*>(W1 + HID) + jg);
        const float4 w1r2 = __ldg(reinterpret_cast<const float4*>(W1 + 2 * HID) + jg);
        const float4 bb1  = __ldg(reinterpret_cast<const float4*>(b1) + jg);
        #pragma unroll
        for (int pp = 0; pp < 8; ++pp) {
            const int p = pg * 8 + pp;
            const float frac = (p + 0.5f) * (1.0f / NS);
            const float t  = tnear + span * frac;
            const float nx = (o0 + t * d0 - mn0) * sclx - 1.0f;
            const float ny = (o1 + t * d1 - mn1) * scly - 1.0f;
            const float nz = (o2 + t * d2 - mn2) * sclz - 1.0f;
            float4 h;
            h.x = fmaxf(nx * w1r0.x + ny * w1r1.x + nz * w1r2.x + bb1.x, 0.0f);
            h.y = fmaxf(nx * w1r0.y + ny * w1r1.y + nz * w1r2.y + bb1.y, 0.0f);
            h.z = fmaxf(nx * w1r0.z + ny * w1r1.z + nz * w1r2.z + bb1.z, 0.0f);
            h.w = fmaxf(nx * w1r0.w + ny * w1r1.w + nz * w1r2.w + bb1.w, 0.0f);
            *reinterpret_cast<float4*>(&h1s[p * HID + j0]) = h;
        }
    }

    // ---------------- Layer 2: h2 = relu(h1 @ W2 + b2) ----------------
    float acc[8][4];
    #pragma unroll
    for (int pp = 0; pp < 8; ++pp)
        #pragma unroll
        for (int c = 0; c < 4; ++c) acc[pp][c] = 0.0f;

    const float4* W2v = reinterpret_cast<const float4*>(W2);
    for (int kt = 0; kt < 8; ++kt) {
        __syncthreads();  // previous tile fully consumed / h1s writes visible
        float4* wsv = reinterpret_cast<float4*>(ws);
        #pragma unroll
        for (int i = 0; i < 8; ++i)
            wsv[tid + i * TPB] = __ldg(&W2v[kt * 2048 + tid + i * TPB]);
        __syncthreads();

        const int kb = kt * 32;
        #pragma unroll
        for (int kk = 0; kk < 32; ++kk) {
            const float4 w = *reinterpret_cast<const float4*>(&ws[kk * HID + j0]);
            #pragma unroll
            for (int pp = 0; pp < 8; ++pp) {
                const float hv = h1s[(pg * 8 + pp) * HID + kb + kk];  // broadcast
                acc[pp][0] = fmaf(hv, w.x, acc[pp][0]);
                acc[pp][1] = fmaf(hv, w.y, acc[pp][1]);
                acc[pp][2] = fmaf(hv, w.z, acc[pp][2]);
                acc[pp][3] = fmaf(hv, w.w, acc[pp][3]);
            }
        }
    }

    // ---------------- Layer 3: o = h2 @ W3 (b3 added after reduction) ----------------
    float po[8][4];
    {
        const float4 bb2 = __ldg(reinterpret_cast<const float4*>(b2) + jg);
        const float4* W3v = reinterpret_cast<const float4*>(W3);
        const float4 w3c0 = __ldg(&W3v[j0 + 0]);
        const float4 w3c1 = __ldg(&W3v[j0 + 1]);
        const float4 w3c2 = __ldg(&W3v[j0 + 2]);
        const float4 w3c3 = __ldg(&W3v[j0 + 3]);
        #pragma unroll
        for (int pp = 0; pp < 8; ++pp) {
            const float h0 = fmaxf(acc[pp][0] + bb2.x, 0.0f);
            const float h1v = fmaxf(acc[pp][1] + bb2.y, 0.0f);
            const float h2v = fmaxf(acc[pp][2] + bb2.z, 0.0f);
            const float h3v = fmaxf(acc[pp][3] + bb2.w, 0.0f);
            po[pp][0] = h0 * w3c0.x + h1v * w3c1.x + h2v * w3c2.x + h3v * w3c3.x;
            po[pp][1] = h0 * w3c0.y + h1v * w3c1.y + h2v * w3c2.y + h3v * w3c3.y;
            po[pp][2] = h0 * w3c0.z + h1v * w3c1.z + h2v * w3c2.z + h3v * w3c3.z;
            po[pp][3] = h0 * w3c0.w + h1v * w3c1.w + h2v * w3c2.w + h3v * w3c3.w;
        }
    }

    // Reduce over the 32 lanes (each lane = different jg within the warp)
    #pragma unroll
    for (int off = 16; off > 0; off >>= 1)
        #pragma unroll
        for (int pp = 0; pp < 8; ++pp)
            #pragma unroll
            for (int c = 0; c < 4; ++c)
                po[pp][c] += __shfl_xor_sync(0xffffffffu, po[pp][c], off);

    const int lane = tid & 31, wid = tid >> 5;
    if (lane == 0) {
        #pragma unroll
        for (int pp = 0; pp < 8; ++pp)
            #pragma unroll
            for (int c = 0; c < 4; ++c)
                partials[(wid * 8 + pp) * 4 + c] = po[pp][c];
    }
    __syncthreads();

    // Combine the two warps that share each point group; add b3.
    if (tid < 128) {
        const int p = tid >> 2, c = tid & 3;
        const int g = p >> 3, pp = p & 7;
        const float val = partials[((2 * g) * 8 + pp) * 4 + c]
                        + partials[((2 * g + 1) * 8 + pp) * 4 + c]
                        + b3[c];
        out4[p * 4 + c] = val;
    }
    __syncthreads();

    // ---------------- Compositing (warp 0; lane = sample) ----------------
    if (tid < 32) {
        const float oo = out4[tid * 4 + 0];
        const float sigma = fmaxf(oo, 0.0f) + log1pf(expf(-fabsf(oo)));
        const float cr = 1.0f / (1.0f + expf(-out4[tid * 4 + 1]));
        const float cg = 1.0f / (1.0f + expf(-out4[tid * 4 + 2]));
        const float cb = 1.0f / (1.0f + expf(-out4[tid * 4 + 3]));

        const float ti = tnear + span * ((tid + 0.5f) * (1.0f / NS));
        const float tn = tnear + span * ((tid + 1.5f) * (1.0f / NS));
        const float delta = (tid == NS - 1) ? (tfar_s - ti) : (tn - ti);
        const float s = sigma * delta;

        // inclusive scan of s over lanes
        float csum = s;
        #pragma unroll
        for (int off = 1; off < 32; off <<= 1) {
            const float nbr = __shfl_up_sync(0xffffffffu, csum, off);
            if (tid >= off) csum += nbr;
        }

        const float w = expf(-(csum - s)) * (1.0f - expf(-s));
        float rr = w * cr, gg = w * cg, bb = w * cb;
        #pragma unroll
        for (int off = 16; off > 0; off >>= 1) {
            rr += __shfl_xor_sync(0xffffffffu, rr, off);
            gg += __shfl_xor_sync(0xffffffffu, gg, off);
            bb += __shfl_xor_sync(0xffffffffu, bb, off);
        }
        const float ctot = __shfl_sync(0xffffffffu, csum, 31);
        if (tid == 0)
            reinterpret_cast<float4*>(out)[ray] =
                make_float4(rr, gg, bb, 1.0f - expf(-ctot));
    }
}

extern "C" void kernel_launch(void* const* d_in, const int* in_sizes, int n_in,
                              void* d_out, int out_size)
{
    const float* K    = (const float*)d_in[0];
    const float* T    = (const float*)d_in[1];
    const float* amin = (const float*)d_in[2];
    const float* amax = (const float*)d_in[3];
    const float* W1   = (const float*)d_in[4];
    const float* b1   = (const float*)d_in[5];
    const float* W2   = (const float*)d_in[6];
    const float* b2   = (const float*)d_in[7];
    const float* W3   = (const float*)d_in[8];
    const float* b3   = (const float*)d_in[9];
    float* out = (float*)d_out;

    const size_t shmem = (size_t)(2 * NS * HID + 8 * 8 * 4 + NS * 4) * sizeof(float);
    cudaFuncSetAttribute(nerf_render_kernel,
                         cudaFuncAttributeMaxDynamicSharedMemorySize, (int)shmem);
    nerf_render_kernel<<<IMGW * IMGW, TPB, shmem>>>(
        K, T, amin, amax, W1, b1, W2, b2, W3, b3, out);
}

// round 2
// speedup vs baseline: 1.0533x; 1.0533x over previous
#include <cuda_runtime.h>

#define HID  256
#define NS   32
#define IMGW 128
#define TPB  256

__device__ __forceinline__ unsigned long long pack2(float a, float b) {
    unsigned long long r;
    asm("mov.b64 %0, {%1, %2};" : "=l"(r) : "f"(a), "f"(b));
    return r;
}
__device__ __forceinline__ void ffma2(unsigned long long& d,
                                      unsigned long long a, unsigned long long b) {
    asm("fma.rn.f32x2 %0, %1, %2, %0;" : "+l"(d) : "l"(a), "l"(b));
}
__device__ __forceinline__ float2 unpack2(unsigned long long v) {
    float2 f;
    asm("mov.b64 {%0, %1}, %2;" : "=f"(f.x), "=f"(f.y) : "l"(v));
    return f;
}

// One ray per block, 256 threads.
// h1 stored K-MAJOR: h1t[k][p] (256 rows x 32 points = 32KB), so point-pairs are
// natural f32x2 register pairs and per-kk reads are 1-2 wavefronts.
// Layer-2 warp mapping: warp w owns cols [32w, 32w+32); lane: (lane&7) -> col quad,
// (lane>>3) -> point octet. Per kk per warp: w = 1 wavefront, hv = 2 wavefronts.
__global__ __launch_bounds__(TPB, 3) void nerf_render_kernel(
    const float* __restrict__ Kmat, const float* __restrict__ T,
    const float* __restrict__ amin, const float* __restrict__ amax,
    const float* __restrict__ W1,   const float* __restrict__ b1,
    const float* __restrict__ W2,   const float* __restrict__ b2,
    const float* __restrict__ W3,   const float* __restrict__ b3,
    float* __restrict__ out)
{
    extern __shared__ float smem[];
    float* h1t = smem;               // [256][32] = 32KB (k-major)
    float* ws  = smem + HID * NS;    // [32][256] = 32KB W2 tile; reused later

    const int tid = threadIdx.x;
    const int ray = blockIdx.x;
    const int px  = ray & (IMGW - 1);
    const int py  = ray >> 7;

    // ---------------- Ray setup ----------------
    const float fx = Kmat[0], fy = Kmat[4], cx = Kmat[2], cy = Kmat[5];
    float u = px + 0.5f, v = py + 0.5f;
    float ddx = (u - cx) / fx, ddy = (v - cy) / fy, ddz = 1.0f;
    float rn = rsqrtf(ddx * ddx + ddy * ddy + ddz * ddz);
    ddx *= rn; ddy *= rn; ddz *= rn;
    const float d0 = T[0] * ddx + T[1] * ddy + T[2]  * ddz;
    const float d1 = T[4] * ddx + T[5] * ddy + T[6]  * ddz;
    const float d2 = T[8] * ddx + T[9] * ddy + T[10] * ddz;
    const float o0 = T[3], o1 = T[7], o2 = T[11];
    const float mn0 = amin[0], mn1 = amin[1], mn2 = amin[2];
    const float mx0 = amax[0], mx1 = amax[1], mx2 = amax[2];

    const float i0 = 1.0f / d0, i1 = 1.0f / d1, i2 = 1.0f / d2;
    const float a0 = (mn0 - o0) * i0, b0v = (mx0 - o0) * i0;
    const float a1 = (mn1 - o1) * i1, b1v = (mx1 - o1) * i1;
    const float a2 = (mn2 - o2) * i2, b2v = (mx2 - o2) * i2;
    const float tnear = fmaxf(0.0f,
        fmaxf(fminf(a0, b0v), fmaxf(fminf(a1, b1v), fminf(a2, b2v))));
    const float tfar = fminf(fmaxf(a0, b0v), fminf(fmaxf(a1, b1v), fmaxf(a2, b2v)));
    if (!(tnear < tfar)) {
        if (tid == 0)
            reinterpret_cast<float4*>(out)[ray] = make_float4(0.f, 0.f, 0.f, 0.f);
        return;
    }
    const float tfar_s = tfar;
    const float span   = tfar_s - tnear;

    const float sclx = 2.0f / (mx0 - mn0);
    const float scly = 2.0f / (mx1 - mn1);
    const float sclz = 2.0f / (mx2 - mn2);

    // ---------------- Layer 1: h1t[k][p] = relu(nxyz @ W1 + b1) ----------------
    {
        const int p  = tid & 31;     // lane == point -> conflict-free stores
        const int cg = tid >> 5;     // 8 col-groups of 32
        const float frac = (p + 0.5f) * (1.0f / NS);
        const float t  = tnear + span * frac;
        const float nx = (o0 + t * d0 - mn0) * sclx - 1.0f;
        const float ny = (o1 + t * d1 - mn1) * scly - 1.0f;
        const float nz = (o2 + t * d2 - mn2) * sclz - 1.0f;
        #pragma unroll
        for (int i = 0; i < 8; ++i) {
            const int c = cg * 32 + i * 4;
            const float4 wx = __ldg(reinterpret_cast<const float4*>(W1) + (c >> 2));
            const float4 wy = __ldg(reinterpret_cast<const float4*>(W1 + HID) + (c >> 2));
            const float4 wz = __ldg(reinterpret_cast<const float4*>(W1 + 2 * HID) + (c >> 2));
            const float4 bb = __ldg(reinterpret_cast<const float4*>(b1) + (c >> 2));
            h1t[(c + 0) * 32 + p] = fmaxf(nx * wx.x + ny * wy.x + nz * wz.x + bb.x, 0.0f);
            h1t[(c + 1) * 32 + p] = fmaxf(nx * wx.y + ny * wy.y + nz * wz.y + bb.y, 0.0f);
            h1t[(c + 2) * 32 + p] = fmaxf(nx * wx.z + ny * wy.z + nz * wz.z + bb.z, 0.0f);
            h1t[(c + 3) * 32 + p] = fmaxf(nx * wx.w + ny * wy.w + nz * wz.w + bb.w, 0.0f);
        }
    }

    // ---------------- Layer 2: h2 = relu(h1 @ W2 + b2), f32x2 packed ----------------
    const int lane = tid & 31;
    const int warp = tid >> 5;
    const int c0   = warp * 32 + (lane & 7) * 4;  // this thread's 4 columns
    const int p0   = (lane >> 3) * 8;             // this thread's 8 points

    unsigned long long acc[4][4];  // [point-pair][col], each = {p even, p odd}
    #pragma unroll
    for (int pr = 0; pr < 4; ++pr)
        #pragma unroll
        for (int q = 0; q < 4; ++q) acc[pr][q] = 0ull;

    const float4* W2v = reinterpret_cast<const float4*>(W2);
    float4* wsv = reinterpret_cast<float4*>(ws);
    for (int kt = 0; kt < 8; ++kt) {
        __syncthreads();
        #pragma unroll
        for (int i = 0; i < 8; ++i)
            wsv[tid + i * TPB] = __ldg(&W2v[kt * 2048 + tid + i * TPB]);
        __syncthreads();

        const float* hrow = h1t + (kt * 32) * 32;
        #pragma unroll 4
        for (int kk = 0; kk < 32; ++kk) {
            const float4 w = *reinterpret_cast<const float4*>(&ws[kk * HID + c0]);
            const unsigned long long wxx = pack2(w.x, w.x);
            const unsigned long long wyy = pack2(w.y, w.y);
            const unsigned long long wzz = pack2(w.z, w.z);
            const unsigned long long www = pack2(w.w, w.w);
            const ulonglong2 ha = *reinterpret_cast<const ulonglong2*>(hrow + kk * 32 + p0);
            const ulonglong2 hb = *reinterpret_cast<const ulonglong2*>(hrow + kk * 32 + p0 + 4);
            ffma2(acc[0][0], ha.x, wxx); ffma2(acc[0][1], ha.x, wyy);
            ffma2(acc[0][2], ha.x, wzz); ffma2(acc[0][3], ha.x, www);
            ffma2(acc[1][0], ha.y, wxx); ffma2(acc[1][1], ha.y, wyy);
            ffma2(acc[1][2], ha.y, wzz); ffma2(acc[1][3], ha.y, www);
            ffma2(acc[2][0], hb.x, wxx); ffma2(acc[2][1], hb.x, wyy);
            ffma2(acc[2][2], hb.x, wzz); ffma2(acc[2][3], hb.x, www);
            ffma2(acc[3][0], hb.y, wxx); ffma2(acc[3][1], hb.y, wyy);
            ffma2(acc[3][2], hb.y, wzz); ffma2(acc[3][3], hb.y, www);
        }
    }
    __syncthreads();  // all ws reads complete before reuse as scratch

    // ---------------- Layer 3: fold h2 @ W3 into 4 channels ----------------
    float po[8][4];
    #pragma unroll
    for (int pp = 0; pp < 8; ++pp)
        #pragma unroll
        for (int c = 0; c < 4; ++c) po[pp][c] = 0.0f;
    {
        const float4 bb2 = __ldg(reinterpret_cast<const float4*>(b2) + (c0 >> 2));
        const float bq[4] = {bb2.x, bb2.y, bb2.z, bb2.w};
        #pragma unroll
        for (int q = 0; q < 4; ++q) {
            const float4 w3 = __ldg(reinterpret_cast<const float4*>(W3) + (c0 + q));
            #pragma unroll
            for (int pr = 0; pr < 4; ++pr) {
                const float2 h2 = unpack2(acc[pr][q]);
                const float ae = fmaxf(h2.x + bq[q], 0.0f);
                const float bo = fmaxf(h2.y + bq[q], 0.0f);
                po[2 * pr][0]     = fmaf(ae, w3.x, po[2 * pr][0]);
                po[2 * pr][1]     = fmaf(ae, w3.y, po[2 * pr][1]);
                po[2 * pr][2]     = fmaf(ae, w3.z, po[2 * pr][2]);
                po[2 * pr][3]     = fmaf(ae, w3.w, po[2 * pr][3]);
                po[2 * pr + 1][0] = fmaf(bo, w3.x, po[2 * pr + 1][0]);
                po[2 * pr + 1][1] = fmaf(bo, w3.y, po[2 * pr + 1][1]);
                po[2 * pr + 1][2] = fmaf(bo, w3.z, po[2 * pr + 1][2]);
                po[2 * pr + 1][3] = fmaf(bo, w3.w, po[2 * pr + 1][3]);
            }
        }
    }
    // reduce across the 8-lane column dimension (lane bits 0..2)
    #pragma unroll
    for (int off = 1; off <= 4; off <<= 1)
        #pragma unroll
        for (int pp = 0; pp < 8; ++pp)
            #pragma unroll
            for (int c = 0; c < 4; ++c)
                po[pp][c] += __shfl_xor_sync(0xffffffffu, po[pp][c], off);

    float* partials = ws;                 // [8 warps][32 pts][4 ch] = 4KB
    float* out4     = ws + 8 * 32 * 4;    // [32 pts][4]
    if ((lane & 7) == 0) {
        float4* pv = reinterpret_cast<float4*>(partials);
        #pragma unroll
        for (int pp = 0; pp < 8; ++pp)
            pv[warp * 32 + p0 + pp] =
                make_float4(po[pp][0], po[pp][1], po[pp][2], po[pp][3]);
    }
    __syncthreads();

    if (tid < 128) {
        const int p = tid >> 2, c = tid & 3;
        float val = b3[c];
        #pragma unroll
        for (int w8 = 0; w8 < 8; ++w8)
            val += partials[(w8 * 32 + p) * 4 + c];
        out4[p * 4 + c] = val;
    }
    __syncthreads();

    // ---------------- Compositing (warp 0; lane = sample) ----------------
    if (tid < 32) {
        const float oo = out4[tid * 4 + 0];
        const float sigma = fmaxf(oo, 0.0f) + log1pf(expf(-fabsf(oo)));
        const float cr = 1.0f / (1.0f + expf(-out4[tid * 4 + 1]));
        const float cg2 = 1.0f / (1.0f + expf(-out4[tid * 4 + 2]));
        const float cb = 1.0f / (1.0f + expf(-out4[tid * 4 + 3]));

        const float ti = tnear + span * ((tid + 0.5f) * (1.0f / NS));
        const float tn = tnear + span * ((tid + 1.5f) * (1.0f / NS));
        const float delta = (tid == NS - 1) ? (tfar_s - ti) : (tn - ti);
        const float s = sigma * delta;

        float csum = s;
        #pragma unroll
        for (int off = 1; off < 32; off <<= 1) {
            const float nbr = __shfl_up_sync(0xffffffffu, csum, off);
            if (tid >= off) csum += nbr;
        }

        const float w = expf(-(csum - s)) * (1.0f - expf(-s));
        float rr = w * cr, gg = w * cg2, bb = w * cb;
        #pragma unroll
        for (int off = 16; off > 0; off >>= 1) {
            rr += __shfl_xor_sync(0xffffffffu, rr, off);
            gg += __shfl_xor_sync(0xffffffffu, gg, off);
            bb += __shfl_xor_sync(0xffffffffu, bb, off);
        }
        const float ctot = __shfl_sync(0xffffffffu, csum, 31);
        if (tid == 0)
            reinterpret_cast<float4*>(out)[ray] =
                make_float4(rr, gg, bb, 1.0f - expf(-ctot));
    }
}

extern "C" void kernel_launch(void* const* d_in, const int* in_sizes, int n_in,
                              void* d_out, int out_size)
{
    const float* K    = (const float*)d_in[0];
    const float* T    = (const float*)d_in[1];
    const float* amin = (const float*)d_in[2];
    const float* amax = (const float*)d_in[3];
    const float* W1   = (const float*)d_in[4];
    const float* b1   = (const float*)d_in[5];
    const float* W2   = (const float*)d_in[6];
    const float* b2   = (const float*)d_in[7];
    const float* W3   = (const float*)d_in[8];
    const float* b3   = (const float*)d_in[9];
    float* out = (float*)d_out;

    const size_t shmem = (size_t)(2 * HID * NS) * sizeof(float);
    cudaFuncSetAttribute(nerf_render_kernel,
                         cudaFuncAttributeMaxDynamicSharedMemorySize, (int)shmem);
    nerf_render_kernel<<<IMGW * IMGW, TPB, shmem>>>(
        K, T, amin, amax, W1, b1, W2, b2, W3, b3, out);
}

// round 5
// speedup vs baseline: 2.6463x; 2.5123x over previous
#include <cuda_runtime.h>
#include <cstdint>

#define HID   256
#define NS    32
#define IMGW  128
#define TPB   256
#define RPB   4
#define MDIM  128
#define A_BYTES 131072            // A fragment layout: [32 sg][8 f][32 lane][4 f32]
#define B_OFF   131072            // B chunk fragment layout: [4 s][32 nf][32 lane][2 f32]
#define SMEM_BYTES (A_BYTES + 32768)

__device__ __forceinline__ uint32_t f2tf32(float f) {
    uint32_t u; asm("cvt.rna.tf32.f32 %0, %1;" : "=r"(u) : "f"(f)); return u;
}
__device__ __forceinline__ void mma8(float* d, const uint32_t* a, const uint32_t* b) {
    asm("mma.sync.aligned.m16n8k8.row.col.f32.tf32.tf32.f32 "
        "{%0,%1,%2,%3}, {%4,%5,%6,%7}, {%8,%9}, {%0,%1,%2,%3};"
        : "+f"(d[0]), "+f"(d[1]), "+f"(d[2]), "+f"(d[3])
        : "r"(a[0]), "r"(a[1]), "r"(a[2]), "r"(a[3]), "r"(b[0]), "r"(b[1]));
}

struct RayGeom {
    float o0, o1, o2, d0, d1, d2, tnear, span, tfar_s;
    bool hit;
};

__device__ __forceinline__ RayGeom ray_geom(
    int ray, const float* Kmat, const float* T,
    const float* amin, const float* amax)
{
    RayGeom g;
    const int px = ray & (IMGW - 1), py = ray >> 7;
    const float fx = Kmat[0], fy = Kmat[4], cx = Kmat[2], cy = Kmat[5];
    float ddx = (px + 0.5f - cx) / fx, ddy = (py + 0.5f - cy) / fy, ddz = 1.0f;
    const float rn = rsqrtf(ddx * ddx + ddy * ddy + ddz * ddz);
    ddx *= rn; ddy *= rn; ddz *= rn;
    g.d0 = T[0] * ddx + T[1] * ddy + T[2]  * ddz;
    g.d1 = T[4] * ddx + T[5] * ddy + T[6]  * ddz;
    g.d2 = T[8] * ddx + T[9] * ddy + T[10] * ddz;
    g.o0 = T[3]; g.o1 = T[7]; g.o2 = T[11];
    const float i0 = 1.0f / g.d0, i1 = 1.0f / g.d1, i2 = 1.0f / g.d2;
    const float a0 = (amin[0] - g.o0) * i0, b0 = (amax[0] - g.o0) * i0;
    const float a1 = (amin[1] - g.o1) * i1, b1 = (amax[1] - g.o1) * i1;
    const float a2 = (amin[2] - g.o2) * i2, b2 = (amax[2] - g.o2) * i2;
    g.tnear = fmaxf(0.0f,
        fmaxf(fminf(a0, b0), fmaxf(fminf(a1, b1), fminf(a2, b2))));
    const float tfar = fminf(fmaxf(a0, b0), fminf(fmaxf(a1, b1), fmaxf(a2, b2)));
    g.hit    = g.tnear < tfar;
    g.tfar_s = g.hit ? tfar : (g.tnear + 1.0f);
    g.span   = g.tfar_s - g.tnear;
    return g;
}

__global__ __launch_bounds__(TPB, 1) void nerf_hmma_kernel(
    const float* __restrict__ Kmat, const float* __restrict__ T,
    const float* __restrict__ amin, const float* __restrict__ amax,
    const float* __restrict__ W1,   const float* __restrict__ b1,
    const float* __restrict__ W2,   const float* __restrict__ b2,
    const float* __restrict__ W3,   const float* __restrict__ b3,
    float* __restrict__ out)
{
    extern __shared__ unsigned char smem[];

    const int tid  = threadIdx.x;
    const int warp = tid >> 5;
    const int lane = tid & 31;

    // ---------- B prefetch for chunk 0 (overlaps layer-1 compute) ----------
    float pre[32];
    {
        #pragma unroll
        for (int i = 0; i < 16; ++i) {
            const int p  = warp * 16 + i;
            const int nf = p & 31;
            const int kb = (p >> 5) * 8 + (lane & 3);      // chunk 0
            const int n  = nf * 8 + (lane >> 2);
            pre[2 * i]     = __ldg(W2 + (kb)     * HID + n);
            pre[2 * i + 1] = __ldg(W2 + (kb + 4) * HID + n);
        }
    }

    // ---------- Layer 1 -> A fragments ----------
    // warp w owns mfrag f=w (rows 16w..16w+15). Thread rows: r0=16w+lane/4, r1=r0+8.
    // Both rows belong to ray w/2. Slot (sg, w, lane) = {A[r0][c0],A[r1][c0],A[r0][c1],A[r1][c1]},
    // c0 = 8*sg + lane%4, c1 = c0+4.
    {
        const int ray = blockIdx.x * RPB + (warp >> 1);
        const RayGeom g = ray_geom(ray, Kmat, T, amin, amax);
        const float sclx = 2.0f / (amax[0] - amin[0]);
        const float scly = 2.0f / (amax[1] - amin[1]);
        const float sclz = 2.0f / (amax[2] - amin[2]);
        const int m0 = warp * 16 + (lane >> 2);
        float nx[2], ny[2], nz[2];
        #pragma unroll
        for (int rh = 0; rh < 2; ++rh) {
            const int p = (m0 + 8 * rh) & 31;
            const float t = g.tnear + g.span * ((p + 0.5f) * (1.0f / NS));
            nx[rh] = (g.o0 + t * g.d0 - amin[0]) * sclx - 1.0f;
            ny[rh] = (g.o1 + t * g.d1 - amin[1]) * scly - 1.0f;
            nz[rh] = (g.o2 + t * g.d2 - amin[2]) * sclz - 1.0f;
        }
        #pragma unroll 4
        for (int sg = 0; sg < 32; ++sg) {
            const int c0 = sg * 8 + (lane & 3);
            uint4 st;
            #pragma unroll
            for (int ch = 0; ch < 2; ++ch) {
                const int c = c0 + 4 * ch;
                const float wx = __ldg(W1 + c);
                const float wy = __ldg(W1 + HID + c);
                const float wz = __ldg(W1 + 2 * HID + c);
                const float bb = __ldg(b1 + c);
                const float v0 = fmaxf(fmaf(nx[0], wx, fmaf(ny[0], wy, fmaf(nz[0], wz, bb))), 0.0f);
                const float v1 = fmaxf(fmaf(nx[1], wx, fmaf(ny[1], wy, fmaf(nz[1], wz, bb))), 0.0f);
                if (ch == 0) { st.x = f2tf32(v0); st.y = f2tf32(v1); }
                else         { st.z = f2tf32(v0); st.w = f2tf32(v1); }
            }
            *reinterpret_cast<uint4*>(smem + ((sg * 8 + warp) * 32 + lane) * 16) = st;
        }
    }

    // ---------- Layer 2 GEMM: [128x256] @ [256x256], tf32 HMMA ----------
    const int mwarp = warp & 1;       // 2 warps along M
    const int nwarp = warp >> 1;      // 4 warps along N
    float acc[4][8][4];
    #pragma unroll
    for (int f = 0; f < 4; ++f)
        #pragma unroll
        for (int j = 0; j < 8; ++j)
            #pragma unroll
            for (int r = 0; r < 4; ++r) acc[f][j][r] = 0.0f;

    #pragma unroll 1
    for (int kc = 0; kc < 8; ++kc) {
        __syncthreads();   // prior chunk's B reads done (kc=0: A writes done too)
        #pragma unroll
        for (int i = 0; i < 16; ++i) {
            const int p = warp * 16 + i;
            uint2 st;
            st.x = f2tf32(pre[2 * i]);
            st.y = f2tf32(pre[2 * i + 1]);
            *reinterpret_cast<uint2*>(smem + B_OFF + (p * 32 + lane) * 8) = st;
        }
        __syncthreads();

        if (kc < 7) {      // prefetch next chunk (latency hides under MMA)
            #pragma unroll
            for (int i = 0; i < 16; ++i) {
                const int p  = warp * 16 + i;
                const int nf = p & 31;
                const int kb = (kc + 1) * 32 + (p >> 5) * 8 + (lane & 3);
                const int n  = nf * 8 + (lane >> 2);
                pre[2 * i]     = __ldg(W2 + (kb)     * HID + n);
                pre[2 * i + 1] = __ldg(W2 + (kb + 4) * HID + n);
            }
        }

        #pragma unroll
        for (int s = 0; s < 4; ++s) {
            const int sg = kc * 4 + s;
            uint4 aF[4];
            uint2 bF[8];
            #pragma unroll
            for (int f = 0; f < 4; ++f)
                aF[f] = *reinterpret_cast<const uint4*>(
                    smem + ((sg * 8 + mwarp * 4 + f) * 32 + lane) * 16);
            #pragma unroll
            for (int j = 0; j < 8; ++j)
                bF[j] = *reinterpret_cast<const uint2*>(
                    smem + B_OFF + ((s * 32 + nwarp * 8 + j) * 32 + lane) * 8);
            #pragma unroll
            for (int f = 0; f < 4; ++f)
                #pragma unroll
                for (int j = 0; j < 8; ++j)
                    mma8(acc[f][j], reinterpret_cast<const uint32_t*>(&aF[f]),
                         reinterpret_cast<const uint32_t*>(&bF[j]));
        }
    }
    __syncthreads();   // all B/A reads done; smem reusable

    // ---------- Layer 3 fold: po[8 rows][4 ch] per thread ----------
    float po[8][4];
    #pragma unroll
    for (int r = 0; r < 8; ++r)
        #pragma unroll
        for (int c = 0; c < 4; ++c) po[r][c] = 0.0f;

    #pragma unroll
    for (int j = 0; j < 8; ++j) {
        const int n0 = (nwarp * 8 + j) * 8 + (lane & 3) * 2;
        const float2 bb = __ldg(reinterpret_cast<const float2*>(b2 + n0));
        const float4 w30 = __ldg(reinterpret_cast<const float4*>(W3) + n0);
        const float4 w31 = __ldg(reinterpret_cast<const float4*>(W3) + n0 + 1);
        #pragma unroll
        for (int f = 0; f < 4; ++f) {
            #pragma unroll
            for (int rh = 0; rh < 2; ++rh) {
                const float h0 = fmaxf(acc[f][j][2 * rh]     + bb.x, 0.0f);
                const float h1 = fmaxf(acc[f][j][2 * rh + 1] + bb.y, 0.0f);
                float* o = po[f * 2 + rh];
                o[0] = fmaf(h0, w30.x, fmaf(h1, w31.x, o[0]));
                o[1] = fmaf(h0, w30.y, fmaf(h1, w31.y, o[1]));
                o[2] = fmaf(h0, w30.z, fmaf(h1, w31.z, o[2]));
                o[3] = fmaf(h0, w30.w, fmaf(h1, w31.w, o[3]));
            }
        }
    }
    // reduce over lane%4 (low two lane bits)
    #pragma unroll
    for (int off = 1; off <= 2; off <<= 1)
        #pragma unroll
        for (int r = 0; r < 8; ++r)
            #pragma unroll
            for (int c = 0; c < 4; ++c)
                po[r][c] += __shfl_xor_sync(0xffffffffu, po[r][c], off);

    float* part = reinterpret_cast<float*>(smem + B_OFF);  // [4 nwarp][128 m][4]
    if ((lane & 3) == 0) {
        #pragma unroll
        for (int f = 0; f < 4; ++f)
            #pragma unroll
            for (int rh = 0; rh < 2; ++rh) {
                const int m = mwarp * 64 + f * 16 + (lane >> 2) + 8 * rh;
                *reinterpret_cast<float4*>(&part[(nwarp * 128 + m) * 4]) =
                    make_float4(po[f * 2 + rh][0], po[f * 2 + rh][1],
                                po[f * 2 + rh][2], po[f * 2 + rh][3]);
            }
    }
    __syncthreads();

    // ---------- Combine + compositing (threads 0..127; warp = ray) ----------
    if (tid < MDIM) {
        float4 v = make_float4(b3[0], b3[1], b3[2], b3[3]);
        #pragma unroll
        for (int w = 0; w < 4; ++w) {
            const float4 p4 = *reinterpret_cast<const float4*>(&part[(w * 128 + tid) * 4]);
            v.x += p4.x; v.y += p4.y; v.z += p4.z; v.w += p4.w;
        }
        const int ray = blockIdx.x * RPB + (tid >> 5);
        const RayGeom g = ray_geom(ray, Kmat, T, amin, amax);

        const float sigma = fmaxf(v.x, 0.0f) + log1pf(expf(-fabsf(v.x)));
        const float cr = 1.0f / (1.0f + expf(-v.y));
        const float cg = 1.0f / (1.0f + expf(-v.z));
        const float cb = 1.0f / (1.0f + expf(-v.w));

        const float ti = g.tnear + g.span * ((lane + 0.5f) * (1.0f / NS));
        const float tn = g.tnear + g.span * ((lane + 1.5f) * (1.0f / NS));
        const float delta = (lane == NS - 1) ? (g.tfar_s - ti) : (tn - ti);
        const float s = sigma * delta;

        float csum = s;
        #pragma unroll
        for (int off = 1; off < 32; off <<= 1) {
            const float nbr = __shfl_up_sync(0xffffffffu, csum, off);
            if (lane >= off) csum += nbr;
        }
        const float wgt = expf(-(csum - s)) * (1.0f - expf(-s));
        float rr = wgt * cr, gg = wgt * cg, bb = wgt * cb;
        #pragma unroll
        for (int off = 16; off > 0; off >>= 1) {
            rr += __shfl_xor_sync(0xffffffffu, rr, off);
            gg += __shfl_xor_sync(0xffffffffu, gg, off);
            bb += __shfl_xor_sync(0xffffffffu, bb, off);
        }
        const float ctot = __shfl_sync(0xffffffffu, csum, 31);
        if (lane == 0) {
            reinterpret_cast<float4*>(out)[ray] = g.hit
                ? make_float4(rr, gg, bb, 1.0f - expf(-ctot))
                : make_float4(0.f, 0.f, 0.f, 0.f);
        }
    }
}

extern "C" void kernel_launch(void* const* d_in, const int* in_sizes, int n_in,
                              void* d_out, int out_size)
{
    const float* K    = (const float*)d_in[0];
    const float* T    = (const float*)d_in[1];
    const float* amin = (const float*)d_in[2];
    const float* amax = (const float*)d_in[3];
    const float* W1   = (const float*)d_in[4];
    const float* b1   = (const float*)d_in[5];
    const float* W2   = (const float*)d_in[6];
    const float* b2   = (const float*)d_in[7];
    const float* W3   = (const float*)d_in[8];
    const float* b3   = (const float*)d_in[9];
    float* out = (float*)d_out;

    cudaFuncSetAttribute(nerf_hmma_kernel,
                         cudaFuncAttributeMaxDynamicSharedMemorySize, SMEM_BYTES);
    nerf_hmma_kernel<<<(IMGW * IMGW) / RPB, TPB, SMEM_BYTES>>>(
        K, T, amin, amax, W1, b1, W2, b2, W3, b3, out);
}

// round 6
// speedup vs baseline: 3.1675x; 1.1969x over previous
#include <cuda_runtime.h>
#include <cstdint>

#define HID   256
#define NS    32
#define IMGW  128
#define TPB   512
#define RPB   4
#define MDIM  128
#define A_BYTES   131072          // A fragments: [32 sg][8 f][32 lane][4 f32]
#define BSTRIDE   264             // floats per B row (256 + 8 pad -> conflict-free)
#define B_CHUNK_B (32 * BSTRIDE * 4)
#define SMEM_BYTES (A_BYTES + 2 * B_CHUNK_B)

__device__ __forceinline__ uint32_t f2tf32(float f) {
    uint32_t u; asm("cvt.rna.tf32.f32 %0, %1;" : "=r"(u) : "f"(f)); return u;
}
__device__ __forceinline__ void mma8(float* d, const uint32_t* a, const uint32_t* b) {
    asm("mma.sync.aligned.m16n8k8.row.col.f32.tf32.tf32.f32 "
        "{%0,%1,%2,%3}, {%4,%5,%6,%7}, {%8,%9}, {%0,%1,%2,%3};"
        : "+f"(d[0]), "+f"(d[1]), "+f"(d[2]), "+f"(d[3])
        : "r"(a[0]), "r"(a[1]), "r"(a[2]), "r"(a[3]), "r"(b[0]), "r"(b[1]));
}
__device__ __forceinline__ void cp16(uint32_t dst_smem, const void* src) {
    asm volatile("cp.async.ca.shared.global [%0], [%1], 16;"
                 :: "r"(dst_smem), "l"(src));
}
__device__ __forceinline__ void cp_commit() {
    asm volatile("cp.async.commit_group;" ::: "memory");
}
__device__ __forceinline__ void cp_wait0() {
    asm volatile("cp.async.wait_group 0;" ::: "memory");
}

struct RayGeom {
    float o0, o1, o2, d0, d1, d2, tnear, span, tfar_s;
    bool hit;
};

__device__ __forceinline__ RayGeom ray_geom(
    int ray, const float* Kmat, const float* T,
    const float* amin, const float* amax)
{
    RayGeom g;
    const int px = ray & (IMGW - 1), py = ray >> 7;
    const float fx = Kmat[0], fy = Kmat[4], cx = Kmat[2], cy = Kmat[5];
    float ddx = (px + 0.5f - cx) / fx, ddy = (py + 0.5f - cy) / fy, ddz = 1.0f;
    const float rn = rsqrtf(ddx * ddx + ddy * ddy + ddz * ddz);
    ddx *= rn; ddy *= rn; ddz *= rn;
    g.d0 = T[0] * ddx + T[1] * ddy + T[2]  * ddz;
    g.d1 = T[4] * ddx + T[5] * ddy + T[6]  * ddz;
    g.d2 = T[8] * ddx + T[9] * ddy + T[10] * ddz;
    g.o0 = T[3]; g.o1 = T[7]; g.o2 = T[11];
    const float i0 = 1.0f / g.d0, i1 = 1.0f / g.d1, i2 = 1.0f / g.d2;
    const float a0 = (amin[0] - g.o0) * i0, b0 = (amax[0] - g.o0) * i0;
    const float a1 = (amin[1] - g.o1) * i1, b1 = (amax[1] - g.o1) * i1;
    const float a2 = (amin[2] - g.o2) * i2, b2 = (amax[2] - g.o2) * i2;
    g.tnear = fmaxf(0.0f,
        fmaxf(fminf(a0, b0), fmaxf(fminf(a1, b1), fminf(a2, b2))));
    const float tfar = fminf(fmaxf(a0, b0), fminf(fmaxf(a1, b1), fmaxf(a2, b2)));
    g.hit    = g.tnear < tfar;
    g.tfar_s = g.hit ? tfar : (g.tnear + 1.0f);
    g.span   = g.tfar_s - g.tnear;
    return g;
}

__global__ __launch_bounds__(TPB, 1) void nerf_hmma2_kernel(
    const float* __restrict__ Kmat, const float* __restrict__ T,
    const float* __restrict__ amin, const float* __restrict__ amax,
    const float* __restrict__ W1,   const float* __restrict__ b1,
    const float* __restrict__ W2,   const float* __restrict__ b2,
    const float* __restrict__ W3,   const float* __restrict__ b3,
    float* __restrict__ out)
{
    extern __shared__ unsigned char smem[];
    const uint32_t smem_u = (uint32_t)__cvta_generic_to_shared(smem);

    const int tid  = threadIdx.x;
    const int warp = tid >> 5;
    const int lane = tid & 31;

    // ---------- Prologue: cp.async B chunk 0 into buffer 0 ----------
    {
        #pragma unroll
        for (int i = 0; i < 4; ++i) {
            const int seg = tid + i * TPB;             // 2048 segs of 16B
            const int row = seg >> 6, c16 = seg & 63;
            cp16(smem_u + A_BYTES + row * (BSTRIDE * 4) + c16 * 16,
                 W2 + row * HID + c16 * 4);
        }
        cp_commit();
    }

    // ---------- Layer 1 -> A fragments ----------
    // m-frag f = warp>>1 (rows 16f..16f+15); the two warps of a pair split sg.
    {
        const int f    = warp >> 1;
        const int half = warp & 1;
        const int ray  = blockIdx.x * RPB + (f >> 1);
        const RayGeom g = ray_geom(ray, Kmat, T, amin, amax);
        const float sclx = 2.0f / (amax[0] - amin[0]);
        const float scly = 2.0f / (amax[1] - amin[1]);
        const float sclz = 2.0f / (amax[2] - amin[2]);
        const int r0 = f * 16 + (lane >> 2);
        float nx[2], ny[2], nz[2];
        #pragma unroll
        for (int rh = 0; rh < 2; ++rh) {
            const int p = (r0 + 8 * rh) & 31;
            const float t = g.tnear + g.span * ((p + 0.5f) * (1.0f / NS));
            nx[rh] = (g.o0 + t * g.d0 - amin[0]) * sclx - 1.0f;
            ny[rh] = (g.o1 + t * g.d1 - amin[1]) * scly - 1.0f;
            nz[rh] = (g.o2 + t * g.d2 - amin[2]) * sclz - 1.0f;
        }
        #pragma unroll 4
        for (int sgi = 0; sgi < 16; ++sgi) {
            const int sg = half * 16 + sgi;
            const int c0 = sg * 8 + (lane & 3);
            uint4 st;
            #pragma unroll
            for (int ch = 0; ch < 2; ++ch) {
                const int c = c0 + 4 * ch;
                const float wx = __ldg(W1 + c);
                const float wy = __ldg(W1 + HID + c);
                const float wz = __ldg(W1 + 2 * HID + c);
                const float bb = __ldg(b1 + c);
                const float v0 = fmaxf(fmaf(nx[0], wx, fmaf(ny[0], wy, fmaf(nz[0], wz, bb))), 0.0f);
                const float v1 = fmaxf(fmaf(nx[1], wx, fmaf(ny[1], wy, fmaf(nz[1], wz, bb))), 0.0f);
                if (ch == 0) { st.x = f2tf32(v0); st.y = f2tf32(v1); }
                else         { st.z = f2tf32(v0); st.w = f2tf32(v1); }
            }
            *reinterpret_cast<uint4*>(smem + ((sg * 8 + f) * 32 + lane) * 16) = st;
        }
    }

    // ---------- Layer 2 GEMM: [128x256] @ [256x256], tf32 HMMA ----------
    const int mwarp = warp & 3;       // 4 warps along M (warp tile 32 rows)
    const int nwarp = warp >> 2;      // 4 warps along N (warp tile 64 cols)
    float acc[2][8][4];
    #pragma unroll
    for (int f = 0; f < 2; ++f)
        #pragma unroll
        for (int j = 0; j < 8; ++j)
            #pragma unroll
            for (int r = 0; r < 4; ++r) acc[f][j][r] = 0.0f;

    #pragma unroll 1
    for (int kc = 0; kc < 8; ++kc) {
        cp_wait0();          // chunk kc landed (this thread's groups)
        __syncthreads();     // visible to all; all warps done reading chunk kc-1

        if (kc < 7) {        // prefetch chunk kc+1 into other buffer
            const uint32_t dstb = smem_u + A_BYTES + ((kc + 1) & 1) * B_CHUNK_B;
            const float* srcb = W2 + (kc + 1) * 32 * HID;
            #pragma unroll
            for (int i = 0; i < 4; ++i) {
                const int seg = tid + i * TPB;
                const int row = seg >> 6, c16 = seg & 63;
                cp16(dstb + row * (BSTRIDE * 4) + c16 * 16,
                     srcb + row * HID + c16 * 4);
            }
            cp_commit();
        }

        const float* bbuf = reinterpret_cast<const float*>(
            smem + A_BYTES + (kc & 1) * B_CHUNK_B);
        #pragma unroll
        for (int s = 0; s < 4; ++s) {
            const int sg = kc * 4 + s;
            uint4 aF[2];
            #pragma unroll
            for (int f = 0; f < 2; ++f)
                aF[f] = *reinterpret_cast<const uint4*>(
                    smem + ((sg * 8 + mwarp * 2 + f) * 32 + lane) * 16);
            const int krow = s * 8 + (lane & 3);
            const int nbase = nwarp * 64 + (lane >> 2);
            #pragma unroll
            for (int j = 0; j < 8; ++j) {
                uint32_t bF[2];
                bF[0] = __float_as_uint(bbuf[krow * BSTRIDE + nbase + j * 8]);
                bF[1] = __float_as_uint(bbuf[(krow + 4) * BSTRIDE + nbase + j * 8]);
                mma8(acc[0][j], reinterpret_cast<const uint32_t*>(&aF[0]), bF);
                mma8(acc[1][j], reinterpret_cast<const uint32_t*>(&aF[1]), bF);
            }
        }
    }
    __syncthreads();   // all smem reads done; B region reusable

    // ---------- Layer 3 fold: po[4 rows][4 ch] per thread ----------
    float po[4][4];
    #pragma unroll
    for (int r = 0; r < 4; ++r)
        #pragma unroll
        for (int c = 0; c < 4; ++c) po[r][c] = 0.0f;

    #pragma unroll
    for (int j = 0; j < 8; ++j) {
        const int n0 = (nwarp * 8 + j) * 8 + (lane & 3) * 2;
        const float2 bb = __ldg(reinterpret_cast<const float2*>(b2 + n0));
        const float4 w30 = __ldg(reinterpret_cast<const float4*>(W3) + n0);
        const float4 w31 = __ldg(reinterpret_cast<const float4*>(W3) + n0 + 1);
        #pragma unroll
        for (int f = 0; f < 2; ++f) {
            #pragma unroll
            for (int rh = 0; rh < 2; ++rh) {
                const float h0 = fmaxf(acc[f][j][2 * rh]     + bb.x, 0.0f);
                const float h1 = fmaxf(acc[f][j][2 * rh + 1] + bb.y, 0.0f);
                float* o = po[f * 2 + rh];
                o[0] = fmaf(h0, w30.x, fmaf(h1, w31.x, o[0]));
                o[1] = fmaf(h0, w30.y, fmaf(h1, w31.y, o[1]));
                o[2] = fmaf(h0, w30.z, fmaf(h1, w31.z, o[2]));
                o[3] = fmaf(h0, w30.w, fmaf(h1, w31.w, o[3]));
            }
        }
    }
    #pragma unroll
    for (int off = 1; off <= 2; off <<= 1)
        #pragma unroll
        for (int r = 0; r < 4; ++r)
            #pragma unroll
            for (int c = 0; c < 4; ++c)
                po[r][c] += __shfl_xor_sync(0xffffffffu, po[r][c], off);

    float* part = reinterpret_cast<float*>(smem + A_BYTES);  // [4 nwarp][128 m][4]
    if ((lane & 3) == 0) {
        #pragma unroll
        for (int f = 0; f < 2; ++f)
            #pragma unroll
            for (int rh = 0; rh < 2; ++rh) {
                const int m = mwarp * 32 + f * 16 + (lane >> 2) + 8 * rh;
                *reinterpret_cast<float4*>(&part[(nwarp * MDIM + m) * 4]) =
                    make_float4(po[f * 2 + rh][0], po[f * 2 + rh][1],
                                po[f * 2 + rh][2], po[f * 2 + rh][3]);
            }
    }
    __syncthreads();

    // ---------- Combine + compositing (threads 0..127; warp = ray) ----------
    if (tid < MDIM) {
        float4 v = make_float4(b3[0], b3[1], b3[2], b3[3]);
        #pragma unroll
        for (int w = 0; w < 4; ++w) {
            const float4 p4 = *reinterpret_cast<const float4*>(&part[(w * MDIM + tid) * 4]);
            v.x += p4.x; v.y += p4.y; v.z += p4.z; v.w += p4.w;
        }
        const int ray = blockIdx.x * RPB + (tid >> 5);
        const RayGeom g = ray_geom(ray, Kmat, T, amin, amax);

        const float sigma = fmaxf(v.x, 0.0f) + log1pf(expf(-fabsf(v.x)));
        const float cr = 1.0f / (1.0f + expf(-v.y));
        const float cg = 1.0f / (1.0f + expf(-v.z));
        const float cb = 1.0f / (1.0f + expf(-v.w));

        const float ti = g.tnear + g.span * ((lane + 0.5f) * (1.0f / NS));
        const float tn = g.tnear + g.span * ((lane + 1.5f) * (1.0f / NS));
        const float delta = (lane == NS - 1) ? (g.tfar_s - ti) : (tn - ti);
        const float s = sigma * delta;

        float csum = s;
        #pragma unroll
        for (int off = 1; off < 32; off <<= 1) {
            const float nbr = __shfl_up_sync(0xffffffffu, csum, off);
            if (lane >= off) csum += nbr;
        }
        const float wgt = expf(-(csum - s)) * (1.0f - expf(-s));
        float rr = wgt * cr, gg = wgt * cg, bb = wgt * cb;
        #pragma unroll
        for (int off = 16; off > 0; off >>= 1) {
            rr += __shfl_xor_sync(0xffffffffu, rr, off);
            gg += __shfl_xor_sync(0xffffffffu, gg, off);
            bb += __shfl_xor_sync(0xffffffffu, bb, off);
        }
        const float ctot = __shfl_sync(0xffffffffu, csum, 31);
        if (lane == 0) {
            reinterpret_cast<float4*>(out)[ray] = g.hit
                ? make_float4(rr, gg, bb, 1.0f - expf(-ctot))
                : make_float4(0.f, 0.f, 0.f, 0.f);
        }
    }
}

extern "C" void kernel_launch(void* const* d_in, const int* in_sizes, int n_in,
                              void* d_out, int out_size)
{
    const float* K    = (const float*)d_in[0];
    const float* T    = (const float*)d_in[1];
    const float* amin = (const float*)d_in[2];
    const float* amax = (const float*)d_in[3];
    const float* W1   = (const float*)d_in[4];
    const float* b1   = (const float*)d_in[5];
    const float* W2   = (const float*)d_in[6];
    const float* b2   = (const float*)d_in[7];
    const float* W3   = (const float*)d_in[8];
    const float* b3   = (const float*)d_in[9];
    float* out = (float*)d_out;

    cudaFuncSetAttribute(nerf_hmma2_kernel,
                         cudaFuncAttributeMaxDynamicSharedMemorySize, SMEM_BYTES);
    nerf_hmma2_kernel<<<(IMGW * IMGW) / RPB, TPB, SMEM_BYTES>>>(
        K, T, amin, amax, W1, b1, W2, b2, W3, b3, out);
}

// round 10
// speedup vs baseline: 4.1360x; 1.3058x over previous
#include <cuda_runtime.h>
#include <cuda_fp16.h>
#include <cstdint>

#define HID   256
#define NS    32
#define IMGW  128
#define TPB   512
#define RPB   4
#define MDIM  128
#define B2_ROWU   264                      // uints per k2-row (256 + 8 pad)
#define B2_CHUNKB (16 * B2_ROWU * 4)       // 16896 B per chunk
#define SMEM_BYTES (2 * B2_CHUNKB)

__device__ __forceinline__ uint32_t packh2(float lo, float hi) {
    uint32_t p;  // cvt d, X, Y: Y -> low half, X -> high half
    asm("cvt.rn.f16x2.f32 %0, %1, %2;" : "=r"(p) : "f"(hi), "f"(lo));
    return p;
}
__device__ __forceinline__ void mma16(float* d, const uint32_t* a,
                                      uint32_t b0, uint32_t b1) {
    asm("mma.sync.aligned.m16n8k16.row.col.f32.f16.f16.f32 "
        "{%0,%1,%2,%3}, {%4,%5,%6,%7}, {%8,%9}, {%0,%1,%2,%3};"
        : "+f"(d[0]), "+f"(d[1]), "+f"(d[2]), "+f"(d[3])
        : "r"(a[0]), "r"(a[1]), "r"(a[2]), "r"(a[3]), "r"(b0), "r"(b1));
}

struct RayGeom {
    float o0, o1, o2, d0, d1, d2, tnear, span, tfar_s;
    bool hit;
};

__device__ __forceinline__ RayGeom ray_geom(
    int ray, const float* Kmat, const float* T,
    const float* amin, const float* amax)
{
    RayGeom g;
    const int px = ray & (IMGW - 1), py = ray >> 7;
    const float fx = Kmat[0], fy = Kmat[4], cx = Kmat[2], cy = Kmat[5];
    float ddx = (px + 0.5f - cx) / fx, ddy = (py + 0.5f - cy) / fy, ddz = 1.0f;
    const float rn = rsqrtf(ddx * ddx + ddy * ddy + ddz * ddz);
    ddx *= rn; ddy *= rn; ddz *= rn;
    g.d0 = T[0] * ddx + T[1] * ddy + T[2]  * ddz;
    g.d1 = T[4] * ddx + T[5] * ddy + T[6]  * ddz;
    g.d2 = T[8] * ddx + T[9] * ddy + T[10] * ddz;
    g.o0 = T[3]; g.o1 = T[7]; g.o2 = T[11];
    const float i0 = 1.0f / g.d0, i1 = 1.0f / g.d1, i2 = 1.0f / g.d2;
    const float a0 = (amin[0] - g.o0) * i0, b0 = (amax[0] - g.o0) * i0;
    const float a1 = (amin[1] - g.o1) * i1, b1 = (amax[1] - g.o1) * i1;
    const float a2 = (amin[2] - g.o2) * i2, b2 = (amax[2] - g.o2) * i2;
    g.tnear = fmaxf(0.0f,
        fmaxf(fminf(a0, b0), fmaxf(fminf(a1, b1), fminf(a2, b2))));
    const float tfar = fminf(fmaxf(a0, b0), fminf(fmaxf(a1, b1), fmaxf(a2, b2)));
    g.hit    = g.tnear < tfar;
    g.tfar_s = g.hit ? tfar : (g.tnear + 1.0f);
    g.span   = g.tfar_s - g.tnear;
    return g;
}

__global__ __launch_bounds__(TPB, 1) void nerf_h16_kernel(
    const float* __restrict__ Kmat, const float* __restrict__ T,
    const float* __restrict__ amin, const float* __restrict__ amax,
    const float* __restrict__ W1,   const float* __restrict__ b1v,
    const float* __restrict__ W2,   const float* __restrict__ b2,
    const float* __restrict__ W3,   const float* __restrict__ b3,
    float* __restrict__ out)
{
    extern __shared__ unsigned char smem[];

    const int tid  = threadIdx.x;
    const int warp = tid >> 5;
    const int lane = tid & 31;
    const int mwarp = warp & 3;       // warp M-tile = rows [mwarp*32, +32) = ray mwarp
    const int nwarp = warp >> 2;      // warp N-tile = cols [nwarp*64, +64)

    // ---------- B chunk staging (8 packed uints per thread) ----------
    const int k2a = tid >> 6;                  // 0..7
    const int n4  = (tid & 63) * 4;
    uint32_t stg[8];

    // stage chunk kc into stg[]
    auto ldg_chunk = [&](int kc) {
        #pragma unroll
        for (int s2 = 0; s2 < 2; ++s2) {
            const int k2 = k2a + 8 * s2;
            const float4 r0 = __ldg(reinterpret_cast<const float4*>(
                W2 + (kc * 32 + 2 * k2) * HID + n4));
            const float4 r1 = __ldg(reinterpret_cast<const float4*>(
                W2 + (kc * 32 + 2 * k2 + 1) * HID + n4));
            stg[s2 * 4 + 0] = packh2(r0.x, r1.x);
            stg[s2 * 4 + 1] = packh2(r0.y, r1.y);
            stg[s2 * 4 + 2] = packh2(r0.z, r1.z);
            stg[s2 * 4 + 3] = packh2(r0.w, r1.w);
        }
    };
    auto sts_chunk = [&](int buf) {
        #pragma unroll
        for (int s2 = 0; s2 < 2; ++s2) {
            const int k2 = k2a + 8 * s2;
            *reinterpret_cast<uint4*>(smem + buf * B2_CHUNKB +
                                      (k2 * B2_ROWU + n4) * 4) =
                make_uint4(stg[s2 * 4 + 0], stg[s2 * 4 + 1],
                           stg[s2 * 4 + 2], stg[s2 * 4 + 3]);
        }
    };

    ldg_chunk(0);

    // ---------- Ray + per-thread sample coords (4 rows of this warp's ray) ----------
    float nx[4], ny[4], nz[4];
    {
        const int ray = blockIdx.x * RPB + mwarp;
        const RayGeom g = ray_geom(ray, Kmat, T, amin, amax);
        const float sclx = 2.0f / (amax[0] - amin[0]);
        const float scly = 2.0f / (amax[1] - amin[1]);
        const float sclz = 2.0f / (amax[2] - amin[2]);
        const int gq = lane >> 2;
        #pragma unroll
        for (int f = 0; f < 2; ++f)
            #pragma unroll
            for (int h = 0; h < 2; ++h) {
                const int lr = f * 2 + h;
                const int p  = f * 16 + gq + 8 * h;   // sample index 0..31
                const float t = g.tnear + g.span * ((p + 0.5f) * (1.0f / NS));
                nx[lr] = (g.o0 + t * g.d0 - amin[0]) * sclx - 1.0f;
                ny[lr] = (g.o1 + t * g.d1 - amin[1]) * scly - 1.0f;
                nz[lr] = (g.o2 + t * g.d2 - amin[2]) * sclz - 1.0f;
            }
    }

    sts_chunk(0);
    __syncthreads();
    ldg_chunk(1);

    // ---------- Mainloop: [128x256]@[256x256] f16 HMMA, A in registers ----------
    float acc[2][8][4];
    #pragma unroll
    for (int f = 0; f < 2; ++f)
        #pragma unroll
        for (int j = 0; j < 8; ++j)
            #pragma unroll
            for (int r = 0; r < 4; ++r) acc[f][j][r] = 0.0f;

    #pragma unroll 1
    for (int kc = 0; kc < 8; ++kc) {
        // Layer-1 A fragments for both k16-steps of this chunk
        uint32_t aF[2][2][4];
        #pragma unroll
        for (int st = 0; st < 2; ++st) {
            const int cb = (kc * 2 + st) * 16 + (lane & 3) * 2;
            const float2 wx0 = __ldg(reinterpret_cast<const float2*>(W1 + cb));
            const float2 wy0 = __ldg(reinterpret_cast<const float2*>(W1 + HID + cb));
            const float2 wz0 = __ldg(reinterpret_cast<const float2*>(W1 + 2 * HID + cb));
            const float2 bb0 = __ldg(reinterpret_cast<const float2*>(b1v + cb));
            const float2 wx1 = __ldg(reinterpret_cast<const float2*>(W1 + cb + 8));
            const float2 wy1 = __ldg(reinterpret_cast<const float2*>(W1 + HID + cb + 8));
            const float2 wz1 = __ldg(reinterpret_cast<const float2*>(W1 + 2 * HID + cb + 8));
            const float2 bb1 = __ldg(reinterpret_cast<const float2*>(b1v + cb + 8));
            #pragma unroll
            for (int f = 0; f < 2; ++f)
                #pragma unroll
                for (int h = 0; h < 2; ++h) {
                    const int lr = f * 2 + h;
                    const float vx = fmaxf(fmaf(nx[lr], wx0.x,
                        fmaf(ny[lr], wy0.x, fmaf(nz[lr], wz0.x, bb0.x))), 0.0f);
                    const float vy = fmaxf(fmaf(nx[lr], wx0.y,
                        fmaf(ny[lr], wy0.y, fmaf(nz[lr], wz0.y, bb0.y))), 0.0f);
                    aF[st][f][h] = packh2(vx, vy);
                    const float ux = fmaxf(fmaf(nx[lr], wx1.x,
                        fmaf(ny[lr], wy1.x, fmaf(nz[lr], wz1.x, bb1.x))), 0.0f);
                    const float uy = fmaxf(fmaf(nx[lr], wx1.y,
                        fmaf(ny[lr], wy1.y, fmaf(nz[lr], wz1.y, bb1.y))), 0.0f);
                    aF[st][f][2 + h] = packh2(ux, uy);
                }
        }

        const uint32_t* bb = reinterpret_cast<const uint32_t*>(
            smem + (kc & 1) * B2_CHUNKB);
        const int nb = nwarp * 64 + (lane >> 2);
        #pragma unroll
        for (int st = 0; st < 2; ++st) {
            const int kp0 = (lane & 3) + st * 8;
            #pragma unroll
            for (int j = 0; j < 8; ++j) {
                const uint32_t bf0 = bb[kp0 * B2_ROWU + nb + j * 8];
                const uint32_t bf1 = bb[(kp0 + 4) * B2_ROWU + nb + j * 8];
                mma16(acc[0][j], aF[st][0], bf0, bf1);
                mma16(acc[1][j], aF[st][1], bf0, bf1);
            }
        }

        if (kc < 7) sts_chunk((kc + 1) & 1);
        __syncthreads();
        if (kc < 6) ldg_chunk(kc + 2);
    }

    // ---------- Layer 3 fold ----------
    float po[4][4];
    #pragma unroll
    for (int r = 0; r < 4; ++r)
        #pragma unroll
        for (int c = 0; c < 4; ++c) po[r][c] = 0.0f;

    #pragma unroll
    for (int j = 0; j < 8; ++j) {
        const int n0 = (nwarp * 8 + j) * 8 + (lane & 3) * 2;
        const float2 bb = __ldg(reinterpret_cast<const float2*>(b2 + n0));
        const float4 w30 = __ldg(reinterpret_cast<const float4*>(W3) + n0);
        const float4 w31 = __ldg(reinterpret_cast<const float4*>(W3) + n0 + 1);
        #pragma unroll
        for (int f = 0; f < 2; ++f) {
            #pragma unroll
            for (int rh = 0; rh < 2; ++rh) {
                const float h0 = fmaxf(acc[f][j][2 * rh]     + bb.x, 0.0f);
                const float h1 = fmaxf(acc[f][j][2 * rh + 1] + bb.y, 0.0f);
                float* o = po[f * 2 + rh];
                o[0] = fmaf(h0, w30.x, fmaf(h1, w31.x, o[0]));
                o[1] = fmaf(h0, w30.y, fmaf(h1, w31.y, o[1]));
                o[2] = fmaf(h0, w30.z, fmaf(h1, w31.z, o[2]));
                o[3] = fmaf(h0, w30.w, fmaf(h1, w31.w, o[3]));
            }
        }
    }
    #pragma unroll
    for (int off = 1; off <= 2; off <<= 1)
        #pragma unroll
        for (int r = 0; r < 4; ++r)
            #pragma unroll
            for (int c = 0; c < 4; ++c)
                po[r][c] += __shfl_xor_sync(0xffffffffu, po[r][c], off);

    float* part = reinterpret_cast<float*>(smem);  // [4 nwarp][128 m][4] = 8KB
    if ((lane & 3) == 0) {
        #pragma unroll
        for (int f = 0; f < 2; ++f)
            #pragma unroll
            for (int rh = 0; rh < 2; ++rh) {
                const int m = mwarp * 32 + f * 16 + (lane >> 2) + 8 * rh;
                *reinterpret_cast<float4*>(&part[(nwarp * MDIM + m) * 4]) =
                    make_float4(po[f * 2 + rh][0], po[f * 2 + rh][1],
                                po[f * 2 + rh][2], po[f * 2 + rh][3]);
            }
    }
    __syncthreads();

    // ---------- Combine + compositing (threads 0..127; warp = ray) ----------
    if (tid < MDIM) {
        float4 v = make_float4(b3[0], b3[1], b3[2], b3[3]);
        #pragma unroll
        for (int w = 0; w < 4; ++w) {
            const float4 p4 = *reinterpret_cast<const float4*>(&part[(w * MDIM + tid) * 4]);
            v.x += p4.x; v.y += p4.y; v.z += p4.z; v.w += p4.w;
        }
        const int ray = blockIdx.x * RPB + (tid >> 5);
        const RayGeom g = ray_geom(ray, Kmat, T, amin, amax);

        const float sigma = fmaxf(v.x, 0.0f) + log1pf(expf(-fabsf(v.x)));
        const float cr = 1.0f / (1.0f + expf(-v.y));
        const float cg = 1.0f / (1.0f + expf(-v.z));
        const float cb = 1.0f / (1.0f + expf(-v.w));

        const float ti = g.tnear + g.span * ((lane + 0.5f) * (1.0f / NS));
        const float tn = g.tnear + g.span * ((lane + 1.5f) * (1.0f / NS));
        const float delta = (lane == NS - 1) ? (g.tfar_s - ti) : (tn - ti);
        const float s = sigma * delta;

        float csum = s;
        #pragma unroll
        for (int off = 1; off < 32; off <<= 1) {
            const float nbr = __shfl_up_sync(0xffffffffu, csum, off);
            if (lane >= off) csum += nbr;
        }
        const float wgt = expf(-(csum - s)) * (1.0f - expf(-s));
        float rr = wgt * cr, gg = wgt * cg, bbv = wgt * cb;
        #pragma unroll
        for (int off = 16; off > 0; off >>= 1) {
            rr  += __shfl_xor_sync(0xffffffffu, rr, off);
            gg  += __shfl_xor_sync(0xffffffffu, gg, off);
            bbv += __shfl_xor_sync(0xffffffffu, bbv, off);
        }
        const float ctot = __shfl_sync(0xffffffffu, csum, 31);
        if (lane == 0) {
            reinterpret_cast<float4*>(out)[ray] = g.hit
                ? make_float4(rr, gg, bbv, 1.0f - expf(-ctot))
                : make_float4(0.f, 0.f, 0.f, 0.f);
        }
    }
}

extern "C" void kernel_launch(void* const* d_in, const int* in_sizes, int n_in,
                              void* d_out, int out_size)
{
    const float* K    = (const float*)d_in[0];
    const float* T    = (const float*)d_in[1];
    const float* amin = (const float*)d_in[2];
    const float* amax = (const float*)d_in[3];
    const float* W1   = (const float*)d_in[4];
    const float* b1   = (const float*)d_in[5];
    const float* W2   = (const float*)d_in[6];
    const float* b2   = (const float*)d_in[7];
    const float* W3   = (const float*)d_in[8];
    const float* b3   = (const float*)d_in[9];
    float* out = (float*)d_out;

    cudaFuncSetAttribute(nerf_h16_kernel,
                         cudaFuncAttributeMaxDynamicSharedMemorySize, SMEM_BYTES);
    nerf_h16_kernel<<<(IMGW * IMGW) / RPB, TPB, SMEM_BYTES>>>(
        K, T, amin, amax, W1, b1, W2, b2, W3, b3, out);
}

// round 12
// speedup vs baseline: 4.7609x; 1.1511x over previous
#include <cuda_runtime.h>
#include <cuda_fp16.h>
#include <cstdint>

#define HID   256
#define NS    32
#define IMGW  128
#define TPB   512
#define RPB   4
#define MDIM  128
#define A_BYTES   65536                    // A fragments: [16 st][8 mf][32 lane] uint4
#define B_OFF     65536
#define B2_ROWU   264                      // uints per k2-row (256 + 8 pad)
#define B2_CHUNKB (16 * B2_ROWU * 4)       // 16896 B per chunk
#define SMEM_BYTES (A_BYTES + 2 * B2_CHUNKB)

__device__ __forceinline__ uint32_t packh2(float lo, float hi) {
    uint32_t p;  // cvt d, X, Y: Y -> low half, X -> high half
    asm("cvt.rn.f16x2.f32 %0, %1, %2;" : "=r"(p) : "f"(hi), "f"(lo));
    return p;
}
__device__ __forceinline__ void mma16(float* d, const uint32_t* a,
                                      uint32_t b0, uint32_t b1) {
    asm("mma.sync.aligned.m16n8k16.row.col.f32.f16.f16.f32 "
        "{%0,%1,%2,%3}, {%4,%5,%6,%7}, {%8,%9}, {%0,%1,%2,%3};"
        : "+f"(d[0]), "+f"(d[1]), "+f"(d[2]), "+f"(d[3])
        : "r"(a[0]), "r"(a[1]), "r"(a[2]), "r"(a[3]), "r"(b0), "r"(b1));
}

struct RayGeom {
    float o0, o1, o2, d0, d1, d2, tnear, span, tfar_s;
    bool hit;
};

__device__ __forceinline__ RayGeom ray_geom(
    int ray, const float* Kmat, const float* T,
    const float* amin, const float* amax)
{
    RayGeom g;
    const int px = ray & (IMGW - 1), py = ray >> 7;
    const float fx = Kmat[0], fy = Kmat[4], cx = Kmat[2], cy = Kmat[5];
    float ddx = (px + 0.5f - cx) / fx, ddy = (py + 0.5f - cy) / fy, ddz = 1.0f;
    const float rn = rsqrtf(ddx * ddx + ddy * ddy + ddz * ddz);
    ddx *= rn; ddy *= rn; ddz *= rn;
    g.d0 = T[0] * ddx + T[1] * ddy + T[2]  * ddz;
    g.d1 = T[4] * ddx + T[5] * ddy + T[6]  * ddz;
    g.d2 = T[8] * ddx + T[9] * ddy + T[10] * ddz;
    g.o0 = T[3]; g.o1 = T[7]; g.o2 = T[11];
    const float i0 = 1.0f / g.d0, i1 = 1.0f / g.d1, i2 = 1.0f / g.d2;
    const float a0 = (amin[0] - g.o0) * i0, b0 = (amax[0] - g.o0) * i0;
    const float a1 = (amin[1] - g.o1) * i1, b1 = (amax[1] - g.o1) * i1;
    const float a2 = (amin[2] - g.o2) * i2, b2 = (amax[2] - g.o2) * i2;
    g.tnear = fmaxf(0.0f,
        fmaxf(fminf(a0, b0), fmaxf(fminf(a1, b1), fminf(a2, b2))));
    const float tfar = fminf(fmaxf(a0, b0), fminf(fmaxf(a1, b1), fmaxf(a2, b2)));
    g.hit    = g.tnear < tfar;
    g.tfar_s = g.hit ? tfar : (g.tnear + 1.0f);
    g.span   = g.tfar_s - g.tnear;
    return g;
}

__global__ __launch_bounds__(TPB, 1) void nerf_h16b_kernel(
    const float* __restrict__ Kmat, const float* __restrict__ T,
    const float* __restrict__ amin, const float* __restrict__ amax,
    const float* __restrict__ W1,   const float* __restrict__ b1v,
    const float* __restrict__ W2,   const float* __restrict__ b2,
    const float* __restrict__ W3,   const float* __restrict__ b3,
    float* __restrict__ out)
{
    extern __shared__ unsigned char smem[];

    const int tid  = threadIdx.x;
    const int warp = tid >> 5;
    const int lane = tid & 31;
    const int mwarp = warp & 3;       // mainloop M-tile: rows [mwarp*32,+32) = ray mwarp
    const int nwarp = warp >> 2;      // mainloop N-tile: cols [nwarp*64,+64)

    // ---------- B chunk staging ----------
    const int k2a = tid >> 6;                  // 0..7
    const int n4  = (tid & 63) * 4;
    uint32_t stg[8];

    auto ldg_chunk = [&](int kc) {
        #pragma unroll
        for (int s2 = 0; s2 < 2; ++s2) {
            const int k2 = k2a + 8 * s2;
            const float4 r0 = __ldg(reinterpret_cast<const float4*>(
                W2 + (kc * 32 + 2 * k2) * HID + n4));
            const float4 r1 = __ldg(reinterpret_cast<const float4*>(
                W2 + (kc * 32 + 2 * k2 + 1) * HID + n4));
            stg[s2 * 4 + 0] = packh2(r0.x, r1.x);
            stg[s2 * 4 + 1] = packh2(r0.y, r1.y);
            stg[s2 * 4 + 2] = packh2(r0.z, r1.z);
            stg[s2 * 4 + 3] = packh2(r0.w, r1.w);
        }
    };
    auto sts_chunk = [&](int buf) {
        #pragma unroll
        for (int s2 = 0; s2 < 2; ++s2) {
            const int k2 = k2a + 8 * s2;
            *reinterpret_cast<uint4*>(smem + B_OFF + buf * B2_CHUNKB +
                                      (k2 * B2_ROWU + n4) * 4) =
                make_uint4(stg[s2 * 4 + 0], stg[s2 * 4 + 1],
                           stg[s2 * 4 + 2], stg[s2 * 4 + 3]);
        }
    };

    ldg_chunk(0);

    // ---------- Build ALL A fragments once (split over 16 warps) ----------
    // warp w: m-frag mf = w&7 (rows 16mf..16mf+15), k-steps st = 8*(w>>3)+i.
    {
        const int mf  = warp & 7;
        const int ray = blockIdx.x * RPB + (mf >> 1);
        const RayGeom g = ray_geom(ray, Kmat, T, amin, amax);
        const float sclx = 2.0f / (amax[0] - amin[0]);
        const float scly = 2.0f / (amax[1] - amin[1]);
        const float sclz = 2.0f / (amax[2] - amin[2]);
        float nxr[2], nyr[2], nzr[2];
        #pragma unroll
        for (int h = 0; h < 2; ++h) {
            const int p = (mf * 16 + (lane >> 2) + 8 * h) & 31;
            const float t = g.tnear + g.span * ((p + 0.5f) * (1.0f / NS));
            nxr[h] = (g.o0 + t * g.d0 - amin[0]) * sclx - 1.0f;
            nyr[h] = (g.o1 + t * g.d1 - amin[1]) * scly - 1.0f;
            nzr[h] = (g.o2 + t * g.d2 - amin[2]) * sclz - 1.0f;
        }
        const int stbase = (warp >> 3) * 8;
        #pragma unroll
        for (int i = 0; i < 8; ++i) {
            const int st = stbase + i;
            const int cb = st * 16 + (lane & 3) * 2;
            const float2 wx0 = __ldg(reinterpret_cast<const float2*>(W1 + cb));
            const float2 wy0 = __ldg(reinterpret_cast<const float2*>(W1 + HID + cb));
            const float2 wz0 = __ldg(reinterpret_cast<const float2*>(W1 + 2 * HID + cb));
            const float2 bb0 = __ldg(reinterpret_cast<const float2*>(b1v + cb));
            const float2 wx1 = __ldg(reinterpret_cast<const float2*>(W1 + cb + 8));
            const float2 wy1 = __ldg(reinterpret_cast<const float2*>(W1 + HID + cb + 8));
            const float2 wz1 = __ldg(reinterpret_cast<const float2*>(W1 + 2 * HID + cb + 8));
            const float2 bb1 = __ldg(reinterpret_cast<const float2*>(b1v + cb + 8));
            uint32_t q[4];
            #pragma unroll
            for (int h = 0; h < 2; ++h) {
                const float v0 = fmaxf(fmaf(nxr[h], wx0.x,
                    fmaf(nyr[h], wy0.x, fmaf(nzr[h], wz0.x, bb0.x))), 0.0f);
                const float v1 = fmaxf(fmaf(nxr[h], wx0.y,
                    fmaf(nyr[h], wy0.y, fmaf(nzr[h], wz0.y, bb0.y))), 0.0f);
                q[h] = packh2(v0, v1);
                const float u0 = fmaxf(fmaf(nxr[h], wx1.x,
                    fmaf(nyr[h], wy1.x, fmaf(nzr[h], wz1.x, bb1.x))), 0.0f);
                const float u1 = fmaxf(fmaf(nxr[h], wx1.y,
                    fmaf(nyr[h], wy1.y, fmaf(nzr[h], wz1.y, bb1.y))), 0.0f);
                q[2 + h] = packh2(u0, u1);
            }
            *reinterpret_cast<uint4*>(smem + ((st * 8 + mf) * 32 + lane) * 16) =
                make_uint4(q[0], q[1], q[2], q[3]);
        }
    }

    sts_chunk(0);
    __syncthreads();          // A fragments + B chunk 0 visible
    ldg_chunk(1);

    // ---------- Mainloop: [128x256]@[256x256] f16 HMMA ----------
    float acc[2][8][4];
    #pragma unroll
    for (int f = 0; f < 2; ++f)
        #pragma unroll
        for (int j = 0; j < 8; ++j)
            #pragma unroll
            for (int r = 0; r < 4; ++r) acc[f][j][r] = 0.0f;

    const int nb = nwarp * 64 + (lane >> 2);
    #pragma unroll 1
    for (int kc = 0; kc < 8; ++kc) {
        const uint32_t* bb = reinterpret_cast<const uint32_t*>(
            smem + B_OFF + (kc & 1) * B2_CHUNKB);
        #pragma unroll
        for (int sti = 0; sti < 2; ++sti) {
            const int st = kc * 2 + sti;
            uint4 aF[2];
            #pragma unroll
            for (int f = 0; f < 2; ++f)
                aF[f] = *reinterpret_cast<const uint4*>(
                    smem + ((st * 8 + mwarp * 2 + f) * 32 + lane) * 16);
            const int kp0 = (lane & 3) + sti * 8;
            #pragma unroll
            for (int j = 0; j < 8; ++j) {
                const uint32_t bf0 = bb[kp0 * B2_ROWU + nb + j * 8];
                const uint32_t bf1 = bb[(kp0 + 4) * B2_ROWU + nb + j * 8];
                mma16(acc[0][j], reinterpret_cast<const uint32_t*>(&aF[0]), bf0, bf1);
                mma16(acc[1][j], reinterpret_cast<const uint32_t*>(&aF[1]), bf0, bf1);
            }
        }
        if (kc < 7) sts_chunk((kc + 1) & 1);
        __syncthreads();
        if (kc < 6) ldg_chunk(kc + 2);
    }

    // ---------- Layer 3 fold ----------
    float po[4][4];
    #pragma unroll
    for (int r = 0; r < 4; ++r)
        #pragma unroll
        for (int c = 0; c < 4; ++c) po[r][c] = 0.0f;

    #pragma unroll
    for (int j = 0; j < 8; ++j) {
        const int n0 = (nwarp * 8 + j) * 8 + (lane & 3) * 2;
        const float2 bb = __ldg(reinterpret_cast<const float2*>(b2 + n0));
        const float4 w30 = __ldg(reinterpret_cast<const float4*>(W3) + n0);
        const float4 w31 = __ldg(reinterpret_cast<const float4*>(W3) + n0 + 1);
        #pragma unroll
        for (int f = 0; f < 2; ++f) {
            #pragma unroll
            for (int rh = 0; rh < 2; ++rh) {
                const float h0 = fmaxf(acc[f][j][2 * rh]     + bb.x, 0.0f);
                const float h1 = fmaxf(acc[f][j][2 * rh + 1] + bb.y, 0.0f);
                float* o = po[f * 2 + rh];
                o[0] = fmaf(h0, w30.x, fmaf(h1, w31.x, o[0]));
                o[1] = fmaf(h0, w30.y, fmaf(h1, w31.y, o[1]));
                o[2] = fmaf(h0, w30.z, fmaf(h1, w31.z, o[2]));
                o[3] = fmaf(h0, w30.w, fmaf(h1, w31.w, o[3]));
            }
        }
    }
    #pragma unroll
    for (int off = 1; off <= 2; off <<= 1)
        #pragma unroll
        for (int r = 0; r < 4; ++r)
            #pragma unroll
            for (int c = 0; c < 4; ++c)
                po[r][c] += __shfl_xor_sync(0xffffffffu, po[r][c], off);

    float* part = reinterpret_cast<float*>(smem + B_OFF);  // [4 nwarp][128 m][4]
    if ((lane & 3) == 0) {
        #pragma unroll
        for (int f = 0; f < 2; ++f)
            #pragma unroll
            for (int rh = 0; rh < 2; ++rh) {
                const int m = mwarp * 32 + f * 16 + (lane >> 2) + 8 * rh;
                *reinterpret_cast<float4*>(&part[(nwarp * MDIM + m) * 4]) =
                    make_float4(po[f * 2 + rh][0], po[f * 2 + rh][1],
                                po[f * 2 + rh][2], po[f * 2 + rh][3]);
            }
    }
    __syncthreads();

    // ---------- Combine + compositing (threads 0..127; warp = ray) ----------
    if (tid < MDIM) {
        float4 v = make_float4(b3[0], b3[1], b3[2], b3[3]);
        #pragma unroll
        for (int w = 0; w < 4; ++w) {
            const float4 p4 = *reinterpret_cast<const float4*>(&part[(w * MDIM + tid) * 4]);
            v.x += p4.x; v.y += p4.y; v.z += p4.z; v.w += p4.w;
        }
        const int ray = blockIdx.x * RPB + (tid >> 5);
        const RayGeom g = ray_geom(ray, Kmat, T, amin, amax);

        const float sigma = fmaxf(v.x, 0.0f) + log1pf(expf(-fabsf(v.x)));
        const float cr = 1.0f / (1.0f + expf(-v.y));
        const float cg = 1.0f / (1.0f + expf(-v.z));
        const float cb = 1.0f / (1.0f + expf(-v.w));

        const float ti = g.tnear + g.span * ((lane + 0.5f) * (1.0f / NS));
        const float tn = g.tnear + g.span * ((lane + 1.5f) * (1.0f / NS));
        const float delta = (lane == NS - 1) ? (g.tfar_s - ti) : (tn - ti);
        const float s = sigma * delta;

        float csum = s;
        #pragma unroll
        for (int off = 1; off < 32; off <<= 1) {
            const float nbr = __shfl_up_sync(0xffffffffu, csum, off);
            if (lane >= off) csum += nbr;
        }
        const float wgt = expf(-(csum - s)) * (1.0f - expf(-s));
        float rr = wgt * cr, gg = wgt * cg, bbv = wgt * cb;
        #pragma unroll
        for (int off = 16; off > 0; off >>= 1) {
            rr  += __shfl_xor_sync(0xffffffffu, rr, off);
            gg  += __shfl_xor_sync(0xffffffffu, gg, off);
            bbv += __shfl_xor_sync(0xffffffffu, bbv, off);
        }
        const float ctot = __shfl_sync(0xffffffffu, csum, 31);
        if (lane == 0) {
            reinterpret_cast<float4*>(out)[ray] = g.hit
                ? make_float4(rr, gg, bbv, 1.0f - expf(-ctot))
                : make_float4(0.f, 0.f, 0.f, 0.f);
        }
    }
}

extern "C" void kernel_launch(void* const* d_in, const int* in_sizes, int n_in,
                              void* d_out, int out_size)
{
    const float* K    = (const float*)d_in[0];
    const float* T    = (const float*)d_in[1];
    const float* amin = (const float*)d_in[2];
    const float* amax = (const float*)d_in[3];
    const float* W1   = (const float*)d_in[4];
    const float* b1   = (const float*)d_in[5];
    const float* W2   = (const float*)d_in[6];
    const float* b2   = (const float*)d_in[7];
    const float* W3   = (const float*)d_in[8];
    const float* b3   = (const float*)d_in[9];
    float* out = (float*)d_out;

    cudaFuncSetAttribute(nerf_h16b_kernel,
                         cudaFuncAttributeMaxDynamicSharedMemorySize, SMEM_BYTES);
    nerf_h16b_kernel<<<(IMGW * IMGW) / RPB, TPB, SMEM_BYTES>>>(
        K, T, amin, amax, W1, b1, W2, b2, W3, b3, out);
}

// round 14
// speedup vs baseline: 6.0743x; 1.2759x over previous
#include <cuda_runtime.h>
#include <cuda_fp16.h>
#include <cstdint>

#define HID   256
#define NS    32
#define IMGW  128
#define TPB   512
#define RPB   4
#define MDIM  128
#define A_BYTES   65536                 // A fragments: [16 st][8 mf][32 lane] uint4
#define B_OFF     65536
#define PAIRROW_U2 258                  // uint2 per (st,kp) row: 256 + 2 pad
#define CHUNK_B   33024                 // 4 steps * 4 kp * 258 * 8 B
#define CHUNK_SEG 2064                  // 16B segments per chunk
#define SMEM_BYTES (B_OFF + 3 * CHUNK_B)   // 164608

// Pre-converted, pre-permuted W2 (f16 pairs in mma B-fragment order).
__device__ __align__(16) uint2 Bp[16 * 4 * PAIRROW_U2];   // 132096 B

__device__ __forceinline__ uint32_t packh2(float lo, float hi) {
    uint32_t p;  // cvt d, X, Y: Y -> low half, X -> high half
    asm("cvt.rn.f16x2.f32 %0, %1, %2;" : "=r"(p) : "f"(hi), "f"(lo));
    return p;
}
__device__ __forceinline__ void mma16(float* d, const uint32_t* a,
                                      uint32_t b0, uint32_t b1) {
    asm("mma.sync.aligned.m16n8k16.row.col.f32.f16.f16.f32 "
        "{%0,%1,%2,%3}, {%4,%5,%6,%7}, {%8,%9}, {%0,%1,%2,%3};"
        : "+f"(d[0]), "+f"(d[1]), "+f"(d[2]), "+f"(d[3])
        : "r"(a[0]), "r"(a[1]), "r"(a[2]), "r"(a[3]), "r"(b0), "r"(b1));
}
__device__ __forceinline__ void cp16cg(uint32_t dst, const void* src) {
    asm volatile("cp.async.cg.shared.global [%0], [%1], 16;"
                 :: "r"(dst), "l"(src));
}

// ---------- prep: W2 (fp32) -> Bp (f16 pairs, fragment order) ----------
__global__ void prep_b_kernel(const float* __restrict__ W2) {
    const int gid = blockIdx.x * blockDim.x + threadIdx.x;   // 16384
    const int st = gid >> 10;
    const int kp = (gid >> 8) & 3;
    const int n  = gid & 255;
    const int r0 = st * 8 + kp, r1 = r0 + 4;
    uint2 u;
    u.x = packh2(W2[2 * r0 * HID + n], W2[(2 * r0 + 1) * HID + n]);
    u.y = packh2(W2[2 * r1 * HID + n], W2[(2 * r1 + 1) * HID + n]);
    const int w = n >> 6, j = (n >> 3) & 7, q = n & 7;
    Bp[(st * 4 + kp) * PAIRROW_U2 + w * 64 + q * 8 + j] = u;
}

struct RayGeom {
    float o0, o1, o2, d0, d1, d2, tnear, span, tfar_s;
    bool hit;
};

__device__ __forceinline__ RayGeom ray_geom(
    int ray, const float* Kmat, const float* T,
    const float* amin, const float* amax)
{
    RayGeom g;
    const int px = ray & (IMGW - 1), py = ray >> 7;
    const float fx = Kmat[0], fy = Kmat[4], cx = Kmat[2], cy = Kmat[5];
    float ddx = (px + 0.5f - cx) / fx, ddy = (py + 0.5f - cy) / fy, ddz = 1.0f;
    const float rn = rsqrtf(ddx * ddx + ddy * ddy + ddz * ddz);
    ddx *= rn; ddy *= rn; ddz *= rn;
    g.d0 = T[0] * ddx + T[1] * ddy + T[2]  * ddz;
    g.d1 = T[4] * ddx + T[5] * ddy + T[6]  * ddz;
    g.d2 = T[8] * ddx + T[9] * ddy + T[10] * ddz;
    g.o0 = T[3]; g.o1 = T[7]; g.o2 = T[11];
    const float i0 = 1.0f / g.d0, i1 = 1.0f / g.d1, i2 = 1.0f / g.d2;
    const float a0 = (amin[0] - g.o0) * i0, b0 = (amax[0] - g.o0) * i0;
    const float a1 = (amin[1] - g.o1) * i1, b1 = (amax[1] - g.o1) * i1;
    const float a2 = (amin[2] - g.o2) * i2, b2 = (amax[2] - g.o2) * i2;
    g.tnear = fmaxf(0.0f,
        fmaxf(fminf(a0, b0), fmaxf(fminf(a1, b1), fminf(a2, b2))));
    const float tfar = fminf(fmaxf(a0, b0), fminf(fmaxf(a1, b1), fmaxf(a2, b2)));
    g.hit    = g.tnear < tfar;
    g.tfar_s = g.hit ? tfar : (g.tnear + 1.0f);
    g.span   = g.tfar_s - g.tnear;
    return g;
}

__global__ __launch_bounds__(TPB, 1) void nerf_h16c_kernel(
    const float* __restrict__ Kmat, const float* __restrict__ T,
    const float* __restrict__ amin, const float* __restrict__ amax,
    const float* __restrict__ W1,   const float* __restrict__ b1v,
    const float* __restrict__ b2,   const float* __restrict__ W3,
    const float* __restrict__ b3,
    float* __restrict__ out)
{
    extern __shared__ unsigned char smem[];
    const uint32_t smem_u = (uint32_t)__cvta_generic_to_shared(smem);

    const int tid  = threadIdx.x;
    const int warp = tid >> 5;
    const int lane = tid & 31;
    const int mwarp = warp & 3;       // rows [mwarp*32,+32) = ray mwarp
    const int nwarp = warp >> 2;      // cols [nwarp*64,+64)

    auto issue_chunk = [&](int kc) {
        const uint32_t dstb = smem_u + B_OFF + (kc % 3) * CHUNK_B;
        const char* srcb = reinterpret_cast<const char*>(Bp) + kc * CHUNK_B;
        #pragma unroll
        for (int i = 0; i < 5; ++i) {
            const int seg = tid + i * TPB;
            if (seg < CHUNK_SEG) cp16cg(dstb + seg * 16, srcb + seg * 16);
        }
        asm volatile("cp.async.commit_group;" ::: "memory");
    };

    issue_chunk(0);
    issue_chunk(1);

    // ---------- Build ALL A fragments once (split over 16 warps) ----------
    {
        const int mf  = warp & 7;
        const int ray = blockIdx.x * RPB + (mf >> 1);
        const RayGeom g = ray_geom(ray, Kmat, T, amin, amax);
        const float sclx = 2.0f / (amax[0] - amin[0]);
        const float scly = 2.0f / (amax[1] - amin[1]);
        const float sclz = 2.0f / (amax[2] - amin[2]);
        float nxr[2], nyr[2], nzr[2];
        #pragma unroll
        for (int h = 0; h < 2; ++h) {
            const int p = (mf * 16 + (lane >> 2) + 8 * h) & 31;
            const float t = g.tnear + g.span * ((p + 0.5f) * (1.0f / NS));
            nxr[h] = (g.o0 + t * g.d0 - amin[0]) * sclx - 1.0f;
            nyr[h] = (g.o1 + t * g.d1 - amin[1]) * scly - 1.0f;
            nzr[h] = (g.o2 + t * g.d2 - amin[2]) * sclz - 1.0f;
        }
        const int stbase = (warp >> 3) * 8;
        #pragma unroll
        for (int i = 0; i < 8; ++i) {
            const int st = stbase + i;
            const int cb = st * 16 + (lane & 3) * 2;
            const float2 wx0 = __ldg(reinterpret_cast<const float2*>(W1 + cb));
            const float2 wy0 = __ldg(reinterpret_cast<const float2*>(W1 + HID + cb));
            const float2 wz0 = __ldg(reinterpret_cast<const float2*>(W1 + 2 * HID + cb));
            const float2 bb0 = __ldg(reinterpret_cast<const float2*>(b1v + cb));
            const float2 wx1 = __ldg(reinterpret_cast<const float2*>(W1 + cb + 8));
            const float2 wy1 = __ldg(reinterpret_cast<const float2*>(W1 + HID + cb + 8));
            const float2 wz1 = __ldg(reinterpret_cast<const float2*>(W1 + 2 * HID + cb + 8));
            const float2 bb1 = __ldg(reinterpret_cast<const float2*>(b1v + cb + 8));
            uint32_t q[4];
            #pragma unroll
            for (int h = 0; h < 2; ++h) {
                const float v0 = fmaxf(fmaf(nxr[h], wx0.x,
                    fmaf(nyr[h], wy0.x, fmaf(nzr[h], wz0.x, bb0.x))), 0.0f);
                const float v1 = fmaxf(fmaf(nxr[h], wx0.y,
                    fmaf(nyr[h], wy0.y, fmaf(nzr[h], wz0.y, bb0.y))), 0.0f);
                q[h] = packh2(v0, v1);
                const float u0 = fmaxf(fmaf(nxr[h], wx1.x,
                    fmaf(nyr[h], wy1.x, fmaf(nzr[h], wz1.x, bb1.x))), 0.0f);
                const float u1 = fmaxf(fmaf(nxr[h], wx1.y,
                    fmaf(nyr[h], wy1.y, fmaf(nzr[h], wz1.y, bb1.y))), 0.0f);
                q[2 + h] = packh2(u0, u1);
            }
            *reinterpret_cast<uint4*>(smem + ((st * 8 + mf) * 32 + lane) * 16) =
                make_uint4(q[0], q[1], q[2], q[3]);
        }
    }

    // ---------- Mainloop: 4 chunks of 64 k, triple-buffered cp.async ----------
    float acc[2][8][4];
    #pragma unroll
    for (int f = 0; f < 2; ++f)
        #pragma unroll
        for (int j = 0; j < 8; ++j)
            #pragma unroll
            for (int r = 0; r < 4; ++r) acc[f][j][r] = 0.0f;

    const int nb2 = nwarp * 64 + (lane >> 2) * 8;   // uint2 column base
    #pragma unroll
    for (int kc = 0; kc < 4; ++kc) {
        if (kc < 3) asm volatile("cp.async.wait_group 1;" ::: "memory");
        else        asm volatile("cp.async.wait_group 0;" ::: "memory");
        __syncthreads();      // chunk kc visible; all warps done with chunk kc-1
        if (kc < 2) issue_chunk(kc + 2);   // into buffer freed at kc-1

        const uint2* bb = reinterpret_cast<const uint2*>(
            smem + B_OFF + (kc % 3) * CHUNK_B);
        #pragma unroll
        for (int stl = 0; stl < 4; ++stl) {
            const int st = kc * 4 + stl;
            uint4 aF[2];
            #pragma unroll
            for (int f = 0; f < 2; ++f)
                aF[f] = *reinterpret_cast<const uint4*>(
                    smem + ((st * 8 + mwarp * 2 + f) * 32 + lane) * 16);
            const uint2* brow = bb + (stl * 4 + (lane & 3)) * PAIRROW_U2 + nb2;
            const uint4 t0 = *reinterpret_cast<const uint4*>(brow);
            const uint4 t1 = *reinterpret_cast<const uint4*>(brow + 2);
            const uint4 t2 = *reinterpret_cast<const uint4*>(brow + 4);
            const uint4 t3 = *reinterpret_cast<const uint4*>(brow + 6);
            mma16(acc[0][0], reinterpret_cast<const uint32_t*>(&aF[0]), t0.x, t0.y);
            mma16(acc[1][0], reinterpret_cast<const uint32_t*>(&aF[1]), t0.x, t0.y);
            mma16(acc[0][1], reinterpret_cast<const uint32_t*>(&aF[0]), t0.z, t0.w);
            mma16(acc[1][1], reinterpret_cast<const uint32_t*>(&aF[1]), t0.z, t0.w);
            mma16(acc[0][2], reinterpret_cast<const uint32_t*>(&aF[0]), t1.x, t1.y);
            mma16(acc[1][2], reinterpret_cast<const uint32_t*>(&aF[1]), t1.x, t1.y);
            mma16(acc[0][3], reinterpret_cast<const uint32_t*>(&aF[0]), t1.z, t1.w);
            mma16(acc[1][3], reinterpret_cast<const uint32_t*>(&aF[1]), t1.z, t1.w);
            mma16(acc[0][4], reinterpret_cast<const uint32_t*>(&aF[0]), t2.x, t2.y);
            mma16(acc[1][4], reinterpret_cast<const uint32_t*>(&aF[1]), t2.x, t2.y);
            mma16(acc[0][5], reinterpret_cast<const uint32_t*>(&aF[0]), t2.z, t2.w);
            mma16(acc[1][5], reinterpret_cast<const uint32_t*>(&aF[1]), t2.z, t2.w);
            mma16(acc[0][6], reinterpret_cast<const uint32_t*>(&aF[0]), t3.x, t3.y);
            mma16(acc[1][6], reinterpret_cast<const uint32_t*>(&aF[1]), t3.x, t3.y);
            mma16(acc[0][7], reinterpret_cast<const uint32_t*>(&aF[0]), t3.z, t3.w);
            mma16(acc[1][7], reinterpret_cast<const uint32_t*>(&aF[1]), t3.z, t3.w);
        }
    }
    __syncthreads();   // all B reads done; B region reusable

    // ---------- Layer 3 fold ----------
    float po[4][4];
    #pragma unroll
    for (int r = 0; r < 4; ++r)
        #pragma unroll
        for (int c = 0; c < 4; ++c) po[r][c] = 0.0f;

    #pragma unroll
    for (int j = 0; j < 8; ++j) {
        const int n0 = (nwarp * 8 + j) * 8 + (lane & 3) * 2;
        const float2 bb = __ldg(reinterpret_cast<const float2*>(b2 + n0));
        const float4 w30 = __ldg(reinterpret_cast<const float4*>(W3) + n0);
        const float4 w31 = __ldg(reinterpret_cast<const float4*>(W3) + n0 + 1);
        #pragma unroll
        for (int f = 0; f < 2; ++f) {
            #pragma unroll
            for (int rh = 0; rh < 2; ++rh) {
                const float h0 = fmaxf(acc[f][j][2 * rh]     + bb.x, 0.0f);
                const float h1 = fmaxf(acc[f][j][2 * rh + 1] + bb.y, 0.0f);
                float* o = po[f * 2 + rh];
                o[0] = fmaf(h0, w30.x, fmaf(h1, w31.x, o[0]));
                o[1] = fmaf(h0, w30.y, fmaf(h1, w31.y, o[1]));
                o[2] = fmaf(h0, w30.z, fmaf(h1, w31.z, o[2]));
                o[3] = fmaf(h0, w30.w, fmaf(h1, w31.w, o[3]));
            }
        }
    }
    #pragma unroll
    for (int off = 1; off <= 2; off <<= 1)
        #pragma unroll
        for (int r = 0; r < 4; ++r)
            #pragma unroll
            for (int c = 0; c < 4; ++c)
                po[r][c] += __shfl_xor_sync(0xffffffffu, po[r][c], off);

    float* part = reinterpret_cast<float*>(smem + B_OFF);  // [4 nwarp][128 m][4]
    if ((lane & 3) == 0) {
        #pragma unroll
        for (int f = 0; f < 2; ++f)
            #pragma unroll
            for (int rh = 0; rh < 2; ++rh) {
                const int m = mwarp * 32 + f * 16 + (lane >> 2) + 8 * rh;
                *reinterpret_cast<float4*>(&part[(nwarp * MDIM + m) * 4]) =
                    make_float4(po[f * 2 + rh][0], po[f * 2 + rh][1],
                                po[f * 2 + rh][2], po[f * 2 + rh][3]);
            }
    }
    __syncthreads();

    // ---------- Combine + compositing (threads 0..127; warp = ray) ----------
    if (tid < MDIM) {
        float4 v = make_float4(b3[0], b3[1], b3[2], b3[3]);
        #pragma unroll
        for (int w = 0; w < 4; ++w) {
            const float4 p4 = *reinterpret_cast<const float4*>(&part[(w * MDIM + tid) * 4]);
            v.x += p4.x; v.y += p4.y; v.z += p4.z; v.w += p4.w;
        }
        const int ray = blockIdx.x * RPB + (tid >> 5);
        const RayGeom g = ray_geom(ray, Kmat, T, amin, amax);

        const float sigma = fmaxf(v.x, 0.0f) + log1pf(expf(-fabsf(v.x)));
        const float cr = 1.0f / (1.0f + expf(-v.y));
        const float cg = 1.0f / (1.0f + expf(-v.z));
        const float cb = 1.0f / (1.0f + expf(-v.w));

        const float ti = g.tnear + g.span * ((lane + 0.5f) * (1.0f / NS));
        const float tn = g.tnear + g.span * ((lane + 1.5f) * (1.0f / NS));
        const float delta = (lane == NS - 1) ? (g.tfar_s - ti) : (tn - ti);
        const float s = sigma * delta;

        float csum = s;
        #pragma unroll
        for (int off = 1; off < 32; off <<= 1) {
            const float nbr = __shfl_up_sync(0xffffffffu, csum, off);
            if (lane >= off) csum += nbr;
        }
        const float wgt = expf(-(csum - s)) * (1.0f - expf(-s));
        float rr = wgt * cr, gg = wgt * cg, bbv = wgt * cb;
        #pragma unroll
        for (int off = 16; off > 0; off >>= 1) {
            rr  += __shfl_xor_sync(0xffffffffu, rr, off);
            gg  += __shfl_xor_sync(0xffffffffu, gg, off);
            bbv += __shfl_xor_sync(0xffffffffu, bbv, off);
        }
        const float ctot = __shfl_sync(0xffffffffu, csum, 31);
        if (lane == 0) {
            reinterpret_cast<float4*>(out)[ray] = g.hit
                ? make_float4(rr, gg, bbv, 1.0f - expf(-ctot))
                : make_float4(0.f, 0.f, 0.f, 0.f);
        }
    }
}

extern "C" void kernel_launch(void* const* d_in, const int* in_sizes, int n_in,
                              void* d_out, int out_size)
{
    const float* K    = (const float*)d_in[0];
    const float* T    = (const float*)d_in[1];
    const float* amin = (const float*)d_in[2];
    const float* amax = (const float*)d_in[3];
    const float* W1   = (const float*)d_in[4];
    const float* b1   = (const float*)d_in[5];
    const float* W2   = (const float*)d_in[6];
    const float* b2   = (const float*)d_in[7];
    const float* W3   = (const float*)d_in[8];
    const float* b3   = (const float*)d_in[9];
    float* out = (float*)d_out;

    prep_b_kernel<<<16, 1024>>>(W2);

    cudaFuncSetAttribute(nerf_h16c_kernel,
                         cudaFuncAttributeMaxDynamicSharedMemorySize, SMEM_BYTES);
    nerf_h16c_kernel<<<(IMGW * IMGW) / RPB, TPB, SMEM_BYTES>>>(
        K, T, amin, amax, W1, b1, b2, W3, b3, out);
}

// round 15
// speedup vs baseline: 7.0695x; 1.1638x over previous
#include <cuda_runtime.h>
#include <cuda_fp16.h>
#include <cstdint>

#define HID   256
#define NS    32
#define IMGW  128
#define TPB   256
#define RPB   2
#define MROWS 64
#define A_BYTES   32768                 // A fragments: [16 st][4 mf][32 lane] uint4
#define PAIRROW_U2 258                  // uint2 per (st,kp) row: 256 + 2 pad
#define CHUNK_B   33024                 // 4 steps * 4 kp * 258 * 8 B
#define CHUNK_SEG 2064                  // 16B segments per chunk
#define SMEM_BYTES (A_BYTES + 2 * CHUNK_B)   // 98816 -> 2 blocks/SM

// Pre-converted, pre-permuted W2 (f16 pairs in mma B-fragment order).
__device__ __align__(16) uint2 Bp[16 * 4 * PAIRROW_U2];   // 132096 B

__device__ __forceinline__ uint32_t packh2(float lo, float hi) {
    uint32_t p;  // cvt d, X, Y: Y -> low half, X -> high half
    asm("cvt.rn.f16x2.f32 %0, %1, %2;" : "=r"(p) : "f"(hi), "f"(lo));
    return p;
}
__device__ __forceinline__ void mma16(float* d, const uint32_t* a,
                                      uint32_t b0, uint32_t b1) {
    asm("mma.sync.aligned.m16n8k16.row.col.f32.f16.f16.f32 "
        "{%0,%1,%2,%3}, {%4,%5,%6,%7}, {%8,%9}, {%0,%1,%2,%3};"
        : "+f"(d[0]), "+f"(d[1]), "+f"(d[2]), "+f"(d[3])
        : "r"(a[0]), "r"(a[1]), "r"(a[2]), "r"(a[3]), "r"(b0), "r"(b1));
}
__device__ __forceinline__ void cp16cg(uint32_t dst, const void* src) {
    asm volatile("cp.async.cg.shared.global [%0], [%1], 16;"
                 :: "r"(dst), "l"(src));
}

// ---------- prep: W2 (fp32) -> Bp (f16 pairs, fragment order) ----------
__global__ void prep_b_kernel(const float* __restrict__ W2) {
    const int gid = blockIdx.x * blockDim.x + threadIdx.x;   // 16384
    const int st = gid >> 10;
    const int kp = (gid >> 8) & 3;
    const int n  = gid & 255;
    const int r0 = st * 8 + kp, r1 = r0 + 4;
    uint2 u;
    u.x = packh2(W2[2 * r0 * HID + n], W2[(2 * r0 + 1) * HID + n]);
    u.y = packh2(W2[2 * r1 * HID + n], W2[(2 * r1 + 1) * HID + n]);
    const int w = n >> 6, j = (n >> 3) & 7, q = n & 7;
    Bp[(st * 4 + kp) * PAIRROW_U2 + w * 64 + q * 8 + j] = u;
}

struct RayGeom {
    float o0, o1, o2, d0, d1, d2, tnear, span, tfar_s;
    bool hit;
};

__device__ __forceinline__ RayGeom ray_geom(
    int ray, const float* Kmat, const float* T,
    const float* amin, const float* amax)
{
    RayGeom g;
    const int px = ray & (IMGW - 1), py = ray >> 7;
    const float fx = Kmat[0], fy = Kmat[4], cx = Kmat[2], cy = Kmat[5];
    float ddx = (px + 0.5f - cx) / fx, ddy = (py + 0.5f - cy) / fy, ddz = 1.0f;
    const float rn = rsqrtf(ddx * ddx + ddy * ddy + ddz * ddz);
    ddx *= rn; ddy *= rn; ddz *= rn;
    g.d0 = T[0] * ddx + T[1] * ddy + T[2]  * ddz;
    g.d1 = T[4] * ddx + T[5] * ddy + T[6]  * ddz;
    g.d2 = T[8] * ddx + T[9] * ddy + T[10] * ddz;
    g.o0 = T[3]; g.o1 = T[7]; g.o2 = T[11];
    const float i0 = 1.0f / g.d0, i1 = 1.0f / g.d1, i2 = 1.0f / g.d2;
    const float a0 = (amin[0] - g.o0) * i0, b0 = (amax[0] - g.o0) * i0;
    const float a1 = (amin[1] - g.o1) * i1, b1 = (amax[1] - g.o1) * i1;
    const float a2 = (amin[2] - g.o2) * i2, b2 = (amax[2] - g.o2) * i2;
    g.tnear = fmaxf(0.0f,
        fmaxf(fminf(a0, b0), fmaxf(fminf(a1, b1), fminf(a2, b2))));
    const float tfar = fminf(fmaxf(a0, b0), fminf(fmaxf(a1, b1), fmaxf(a2, b2)));
    g.hit    = g.tnear < tfar;
    g.tfar_s = g.hit ? tfar : (g.tnear + 1.0f);
    g.span   = g.tfar_s - g.tnear;
    return g;
}

__global__ __launch_bounds__(TPB, 2) void nerf_h16d_kernel(
    const float* __restrict__ Kmat, const float* __restrict__ T,
    const float* __restrict__ amin, const float* __restrict__ amax,
    const float* __restrict__ W1,   const float* __restrict__ b1v,
    const float* __restrict__ b2,   const float* __restrict__ W3,
    const float* __restrict__ b3,
    float* __restrict__ out)
{
    extern __shared__ unsigned char smem[];
    const uint32_t smem_u = (uint32_t)__cvta_generic_to_shared(smem);

    const int tid  = threadIdx.x;
    const int warp = tid >> 5;              // 0..7
    const int lane = tid & 31;
    const int mwarp = warp & 1;             // rows [mwarp*32,+32) = ray mwarp
    const int nwarp = warp >> 1;            // cols [nwarp*64,+64)

    auto issue_chunk = [&](int kc) {
        const uint32_t dstb = smem_u + A_BYTES + (kc & 1) * CHUNK_B;
        const char* srcb = reinterpret_cast<const char*>(Bp) + kc * CHUNK_B;
        #pragma unroll
        for (int i = 0; i < 9; ++i) {
            const int seg = tid + i * TPB;
            if (seg < CHUNK_SEG) cp16cg(dstb + seg * 16, srcb + seg * 16);
        }
        asm volatile("cp.async.commit_group;" ::: "memory");
    };

    issue_chunk(0);
    issue_chunk(1);

    // ---------- Build ALL A fragments once (split over 8 warps) ----------
    // warp w: m-frag mf = w&3 (rows 16mf..16mf+15), k-steps st = (w>>2)*8 + i.
    {
        const int mf  = warp & 3;
        const int ray = blockIdx.x * RPB + (mf >> 1);
        const RayGeom g = ray_geom(ray, Kmat, T, amin, amax);
        const float sclx = 2.0f / (amax[0] - amin[0]);
        const float scly = 2.0f / (amax[1] - amin[1]);
        const float sclz = 2.0f / (amax[2] - amin[2]);
        float nxr[2], nyr[2], nzr[2];
        #pragma unroll
        for (int h = 0; h < 2; ++h) {
            const int p = (mf * 16 + (lane >> 2) + 8 * h) & 31;
            const float t = g.tnear + g.span * ((p + 0.5f) * (1.0f / NS));
            nxr[h] = (g.o0 + t * g.d0 - amin[0]) * sclx - 1.0f;
            nyr[h] = (g.o1 + t * g.d1 - amin[1]) * scly - 1.0f;
            nzr[h] = (g.o2 + t * g.d2 - amin[2]) * sclz - 1.0f;
        }
        const int stbase = (warp >> 2) * 8;
        #pragma unroll
        for (int i = 0; i < 8; ++i) {
            const int st = stbase + i;
            const int cb = st * 16 + (lane & 3) * 2;
            const float2 wx0 = __ldg(reinterpret_cast<const float2*>(W1 + cb));
            const float2 wy0 = __ldg(reinterpret_cast<const float2*>(W1 + HID + cb));
            const float2 wz0 = __ldg(reinterpret_cast<const float2*>(W1 + 2 * HID + cb));
            const float2 bb0 = __ldg(reinterpret_cast<const float2*>(b1v + cb));
            const float2 wx1 = __ldg(reinterpret_cast<const float2*>(W1 + cb + 8));
            const float2 wy1 = __ldg(reinterpret_cast<const float2*>(W1 + HID + cb + 8));
            const float2 wz1 = __ldg(reinterpret_cast<const float2*>(W1 + 2 * HID + cb + 8));
            const float2 bb1 = __ldg(reinterpret_cast<const float2*>(b1v + cb + 8));
            uint32_t q[4];
            #pragma unroll
            for (int h = 0; h < 2; ++h) {
                const float v0 = fmaxf(fmaf(nxr[h], wx0.x,
                    fmaf(nyr[h], wy0.x, fmaf(nzr[h], wz0.x, bb0.x))), 0.0f);
                const float v1 = fmaxf(fmaf(nxr[h], wx0.y,
                    fmaf(nyr[h], wy0.y, fmaf(nzr[h], wz0.y, bb0.y))), 0.0f);
                q[h] = packh2(v0, v1);
                const float u0 = fmaxf(fmaf(nxr[h], wx1.x,
                    fmaf(nyr[h], wy1.x, fmaf(nzr[h], wz1.x, bb1.x))), 0.0f);
                const float u1 = fmaxf(fmaf(nxr[h], wx1.y,
                    fmaf(nyr[h], wy1.y, fmaf(nzr[h], wz1.y, bb1.y))), 0.0f);
                q[2 + h] = packh2(u0, u1);
            }
            *reinterpret_cast<uint4*>(smem + ((st * 4 + mf) * 32 + lane) * 16) =
                make_uint4(q[0], q[1], q[2], q[3]);
        }
    }

    // ---------- Mainloop: 4 chunks of 64 k, double-buffered cp.async ----------
    float acc[2][8][4];
    #pragma unroll
    for (int f = 0; f < 2; ++f)
        #pragma unroll
        for (int j = 0; j < 8; ++j)
            #pragma unroll
            for (int r = 0; r < 4; ++r) acc[f][j][r] = 0.0f;

    const int nb2 = nwarp * 64 + (lane >> 2) * 8;   // uint2 column base
    #pragma unroll
    for (int kc = 0; kc < 4; ++kc) {
        if (kc == 0) asm volatile("cp.async.wait_group 1;" ::: "memory");
        else         asm volatile("cp.async.wait_group 0;" ::: "memory");
        __syncthreads();      // chunk kc visible; all warps done with prev buffer
        if (kc == 1) issue_chunk(2);       // buf0 freed by this barrier
        if (kc == 2) issue_chunk(3);       // buf1 freed by this barrier

        const uint2* bb = reinterpret_cast<const uint2*>(
            smem + A_BYTES + (kc & 1) * CHUNK_B);
        #pragma unroll
        for (int stl = 0; stl < 4; ++stl) {
            const int st = kc * 4 + stl;
            uint4 aF[2];
            #pragma unroll
            for (int f = 0; f < 2; ++f)
                aF[f] = *reinterpret_cast<const uint4*>(
                    smem + ((st * 4 + mwarp * 2 + f) * 32 + lane) * 16);
            const uint2* brow = bb + (stl * 4 + (lane & 3)) * PAIRROW_U2 + nb2;
            const uint4 t0 = *reinterpret_cast<const uint4*>(brow);
            const uint4 t1 = *reinterpret_cast<const uint4*>(brow + 2);
            const uint4 t2 = *reinterpret_cast<const uint4*>(brow + 4);
            const uint4 t3 = *reinterpret_cast<const uint4*>(brow + 6);
            mma16(acc[0][0], reinterpret_cast<const uint32_t*>(&aF[0]), t0.x, t0.y);
            mma16(acc[1][0], reinterpret_cast<const uint32_t*>(&aF[1]), t0.x, t0.y);
            mma16(acc[0][1], reinterpret_cast<const uint32_t*>(&aF[0]), t0.z, t0.w);
            mma16(acc[1][1], reinterpret_cast<const uint32_t*>(&aF[1]), t0.z, t0.w);
            mma16(acc[0][2], reinterpret_cast<const uint32_t*>(&aF[0]), t1.x, t1.y);
            mma16(acc[1][2], reinterpret_cast<const uint32_t*>(&aF[1]), t1.x, t1.y);
            mma16(acc[0][3], reinterpret_cast<const uint32_t*>(&aF[0]), t1.z, t1.w);
            mma16(acc[1][3], reinterpret_cast<const uint32_t*>(&aF[1]), t1.z, t1.w);
            mma16(acc[0][4], reinterpret_cast<const uint32_t*>(&aF[0]), t2.x, t2.y);
            mma16(acc[1][4], reinterpret_cast<const uint32_t*>(&aF[1]), t2.x, t2.y);
            mma16(acc[0][5], reinterpret_cast<const uint32_t*>(&aF[0]), t2.z, t2.w);
            mma16(acc[1][5], reinterpret_cast<const uint32_t*>(&aF[1]), t2.z, t2.w);
            mma16(acc[0][6], reinterpret_cast<const uint32_t*>(&aF[0]), t3.x, t3.y);
            mma16(acc[1][6], reinterpret_cast<const uint32_t*>(&aF[1]), t3.x, t3.y);
            mma16(acc[0][7], reinterpret_cast<const uint32_t*>(&aF[0]), t3.z, t3.w);
            mma16(acc[1][7], reinterpret_cast<const uint32_t*>(&aF[1]), t3.z, t3.w);
        }
    }
    __syncthreads();   // all B reads done; B region reusable

    // ---------- Layer 3 fold ----------
    float po[4][4];
    #pragma unroll
    for (int r = 0; r < 4; ++r)
        #pragma unroll
        for (int c = 0; c < 4; ++c) po[r][c] = 0.0f;

    #pragma unroll
    for (int j = 0; j < 8; ++j) {
        const int n0 = (nwarp * 8 + j) * 8 + (lane & 3) * 2;
        const float2 bb = __ldg(reinterpret_cast<const float2*>(b2 + n0));
        const float4 w30 = __ldg(reinterpret_cast<const float4*>(W3) + n0);
        const float4 w31 = __ldg(reinterpret_cast<const float4*>(W3) + n0 + 1);
        #pragma unroll
        for (int f = 0; f < 2; ++f) {
            #pragma unroll
            for (int rh = 0; rh < 2; ++rh) {
                const float h0 = fmaxf(acc[f][j][2 * rh]     + bb.x, 0.0f);
                const float h1 = fmaxf(acc[f][j][2 * rh + 1] + bb.y, 0.0f);
                float* o = po[f * 2 + rh];
                o[0] = fmaf(h0, w30.x, fmaf(h1, w31.x, o[0]));
                o[1] = fmaf(h0, w30.y, fmaf(h1, w31.y, o[1]));
                o[2] = fmaf(h0, w30.z, fmaf(h1, w31.z, o[2]));
                o[3] = fmaf(h0, w30.w, fmaf(h1, w31.w, o[3]));
            }
        }
    }
    #pragma unroll
    for (int off = 1; off <= 2; off <<= 1)
        #pragma unroll
        for (int r = 0; r < 4; ++r)
            #pragma unroll
            for (int c = 0; c < 4; ++c)
                po[r][c] += __shfl_xor_sync(0xffffffffu, po[r][c], off);

    float* part = reinterpret_cast<float*>(smem + A_BYTES);  // [4 nwarp][64 m][4]
    if ((lane & 3) == 0) {
        #pragma unroll
        for (int f = 0; f < 2; ++f)
            #pragma unroll
            for (int rh = 0; rh < 2; ++rh) {
                const int m = mwarp * 32 + f * 16 + (lane >> 2) + 8 * rh;
                *reinterpret_cast<float4*>(&part[(nwarp * MROWS + m) * 4]) =
                    make_float4(po[f * 2 + rh][0], po[f * 2 + rh][1],
                                po[f * 2 + rh][2], po[f * 2 + rh][3]);
            }
    }
    __syncthreads();

    // ---------- Combine + compositing (threads 0..63; warp-half = ray) ----------
    if (tid < MROWS) {
        float4 v = make_float4(b3[0], b3[1], b3[2], b3[3]);
        #pragma unroll
        for (int w = 0; w < 4; ++w) {
            const float4 p4 = *reinterpret_cast<const float4*>(&part[(w * MROWS + tid) * 4]);
            v.x += p4.x; v.y += p4.y; v.z += p4.z; v.w += p4.w;
        }
        const int ray = blockIdx.x * RPB + (tid >> 5);
        const int cl  = tid & 31;
        const RayGeom g = ray_geom(ray, Kmat, T, amin, amax);

        const float sigma = fmaxf(v.x, 0.0f) + log1pf(expf(-fabsf(v.x)));
        const float cr = 1.0f / (1.0f + expf(-v.y));
        const float cg = 1.0f / (1.0f + expf(-v.z));
        const float cb = 1.0f / (1.0f + expf(-v.w));

        const float ti = g.tnear + g.span * ((cl + 0.5f) * (1.0f / NS));
        const float tn = g.tnear + g.span * ((cl + 1.5f) * (1.0f / NS));
        const float delta = (cl == NS - 1) ? (g.tfar_s - ti) : (tn - ti);
        const float s = sigma * delta;

        float csum = s;
        #pragma unroll
        for (int off = 1; off < 32; off <<= 1) {
            const float nbr = __shfl_up_sync(0xffffffffu, csum, off);
            if (cl >= off) csum += nbr;
        }
        const float wgt = expf(-(csum - s)) * (1.0f - expf(-s));
        float rr = wgt * cr, gg = wgt * cg, bbv = wgt * cb;
        #pragma unroll
        for (int off = 16; off > 0; off >>= 1) {
            rr  += __shfl_xor_sync(0xffffffffu, rr, off);
            gg  += __shfl_xor_sync(0xffffffffu, gg, off);
            bbv += __shfl_xor_sync(0xffffffffu, bbv, off);
        }
        const float ctot = __shfl_sync(0xffffffffu, csum, 31);
        if (cl == 0) {
            reinterpret_cast<float4*>(out)[ray] = g.hit
                ? make_float4(rr, gg, bbv, 1.0f - expf(-ctot))
                : make_float4(0.f, 0.f, 0.f, 0.f);
        }
    }
}

extern "C" void kernel_launch(void* const* d_in, const int* in_sizes, int n_in,
                              void* d_out, int out_size)
{
    const float* K    = (const float*)d_in[0];
    const float* T    = (const float*)d_in[1];
    const float* amin = (const float*)d_in[2];
    const float* amax = (const float*)d_in[3];
    const float* W1   = (const float*)d_in[4];
    const float* b1   = (const float*)d_in[5];
    const float* W2   = (const float*)d_in[6];
    const float* b2   = (const float*)d_in[7];
    const float* W3   = (const float*)d_in[8];
    const float* b3   = (const float*)d_in[9];
    float* out = (float*)d_out;

    prep_b_kernel<<<16, 1024>>>(W2);

    cudaFuncSetAttribute(nerf_h16d_kernel,
                         cudaFuncAttributeMaxDynamicSharedMemorySize, SMEM_BYTES);
    nerf_h16d_kernel<<<(IMGW * IMGW) / RPB, TPB, SMEM_BYTES>>>(
        K, T, amin, amax, W1, b1, b2, W3, b3, out);
}